// round 2
// baseline (speedup 1.0000x reference)
#include <cuda_runtime.h>
#include <math.h>

#define CIN    512
#define COUT   512
#define NB     8
#define HW     4096          // 64*64
#define Mtot   32768         // NB*HW
#define KKtot  4608          // CIN*9
#define NANCH  36864         // HW*9
#define PRE_NMS  2000
#define POST_NMS 300

#define OFF_LOCS   0
#define OFF_SCORES 1179648
#define OFF_ROIS   1769472
#define OFF_IDX    1779072

// ---------------- scratch (device globals; no allocs allowed) ----------------
__device__ float g_h[COUT * Mtot];                       // conv1 output, [cout][m]
__device__ float g_wt[COUT * KKtot];                     // weights re-laid out [k][rs*512+c]
__device__ float g_boxes[NB * NANCH * 4];
__device__ float g_fg[NB * NANCH];
__device__ float g_topbox[NB * PRE_NMS * 4];
__device__ unsigned long long g_mask[NB * PRE_NMS * 32]; // suppression bitmask

// base anchors (ymin,xmin,ymax,xmax), order: ratio-major, scale-minor (matches reference)
__constant__ float c_ba[9][4] = {
    { -37.254833995939045f,  -82.50966799187809f,   53.254833995939045f,  98.50966799187809f },
    { -82.50966799187809f,  -173.01933598375618f,   98.50966799187809f,  189.01933598375618f },
    { -173.01933598375618f, -354.03867196751236f,  189.01933598375618f,  370.03867196751236f },
    { -56.f,  -56.f,   72.f,   72.f },
    { -120.f, -120.f,  136.f,  136.f },
    { -248.f, -248.f,  264.f,  264.f },
    { -82.50966799187809f,   -37.254833995939045f,  98.50966799187809f,   53.254833995939045f },
    { -173.01933598375618f,  -82.50966799187809f,  189.01933598375618f,   98.50966799187809f },
    { -354.03867196751236f, -173.01933598375618f,  370.03867196751236f,  189.01933598375618f },
};

// ---------------- weight transpose: OIHW [k][c*9+rs] -> [k][rs*512+c] ----------------
__global__ void wtrans_kernel(const float* __restrict__ W) {
    int gid = blockIdx.x * blockDim.x + threadIdx.x;
    if (gid >= COUT * KKtot) return;
    int k  = gid / KKtot;
    int t  = gid - k * KKtot;
    int rs = t >> 9;          // 0..8
    int c  = t & 511;
    g_wt[gid] = W[(size_t)k * KKtot + c * 9 + rs];
}

// ---------------- conv1: 3x3 512->512 + bias + ReLU (implicit im2col SGEMM) ----------------
// K-order: rs outer (r ascending, s ascending), c inner ascending.
// Single f32 FMA accumulator per output => accumulation order = (r, s, c).
__global__ __launch_bounds__(256, 2)
void conv1_kernel(const float* __restrict__ X, const float* __restrict__ Bias) {
    __shared__ float As[8][128];
    __shared__ float Bs[8][128];

    int bm  = blockIdx.x;           // 0..255  (m tile)
    int bk  = blockIdx.y;           // 0..3    (out-channel tile)
    int tid = threadIdx.x;
    int tx  = tid & 15, ty = tid >> 4;

    float acc[8][8];
#pragma unroll
    for (int i = 0; i < 8; i++)
#pragma unroll
        for (int j = 0; j < 8; j++) acc[i][j] = 0.f;

    int a_i  = tid >> 1;            // 0..127
    int a_k4 = (tid & 1) * 4;       // 0 or 4
    const float* wrow = g_wt + (size_t)(bk * 128 + a_i) * KKtot + a_k4;
    int m0 = bm * 128;

    // precompute per-thread B-gather m decomposition
    int bj[4], bn[4], byy[4], bxx[4], bkk[4];
#pragma unroll
    for (int e = 0; e < 4; e++) {
        int idx = tid + 256 * e;
        bkk[e] = idx >> 7;
        bj[e]  = idx & 127;
        int m  = m0 + bj[e];
        bn[e]  = m >> 12;
        int p  = m & 4095;
        byy[e] = p >> 6;
        bxx[e] = p & 63;
    }

    for (int rs = 0; rs < 9; rs++) {
        int r = rs / 3, s = rs - 3 * r;
        int dy = r - 1, dx = s - 1;
        for (int c0 = 0; c0 < CIN; c0 += 8) {
            // stage A (re-laid weights): contiguous along c
            float4 av = *reinterpret_cast<const float4*>(wrow + rs * 512 + c0);
            // stage B (im2col gather): 4 elements per thread
            float bv[4];
#pragma unroll
            for (int e = 0; e < 4; e++) {
                int iy = byy[e] + dy, ix = bxx[e] + dx;
                int c  = c0 + bkk[e];
                float v = 0.f;
                if ((unsigned)iy < 64u && (unsigned)ix < 64u)
                    v = X[(((size_t)bn[e] * CIN + c) << 12) + (iy << 6) + ix];
                bv[e] = v;
            }
            __syncthreads();
            As[a_k4 + 0][a_i] = av.x;
            As[a_k4 + 1][a_i] = av.y;
            As[a_k4 + 2][a_i] = av.z;
            As[a_k4 + 3][a_i] = av.w;
#pragma unroll
            for (int e = 0; e < 4; e++)
                Bs[bkk[e]][bj[e]] = bv[e];
            __syncthreads();

#pragma unroll
            for (int kk = 0; kk < 8; kk++) {
                float a[8], b[8];
                *(float4*)(a)     = *(const float4*)&As[kk][ty * 8];
                *(float4*)(a + 4) = *(const float4*)&As[kk][ty * 8 + 4];
                *(float4*)(b)     = *(const float4*)&Bs[kk][tx * 8];
                *(float4*)(b + 4) = *(const float4*)&Bs[kk][tx * 8 + 4];
#pragma unroll
                for (int i = 0; i < 8; i++)
#pragma unroll
                    for (int j = 0; j < 8; j++)
                        acc[i][j] = fmaf(a[i], b[j], acc[i][j]);
            }
        }
    }

    // epilogue: bias + ReLU, write to g_h[k][m]
#pragma unroll
    for (int i = 0; i < 8; i++) {
        int ko = bk * 128 + ty * 8 + i;
        float bias = Bias[ko];
        float4 v0, v1;
        v0.x = fmaxf(acc[i][0] + bias, 0.f);
        v0.y = fmaxf(acc[i][1] + bias, 0.f);
        v0.z = fmaxf(acc[i][2] + bias, 0.f);
        v0.w = fmaxf(acc[i][3] + bias, 0.f);
        v1.x = fmaxf(acc[i][4] + bias, 0.f);
        v1.y = fmaxf(acc[i][5] + bias, 0.f);
        v1.z = fmaxf(acc[i][6] + bias, 0.f);
        v1.w = fmaxf(acc[i][7] + bias, 0.f);
        float* dst = &g_h[(size_t)ko * Mtot + m0 + tx * 8];
        *(float4*)(dst)     = v0;
        *(float4*)(dst + 4) = v1;
    }
}

// ---------------- 1x1 convs: 54 channels (36 loc + 18 score), write into d_out ----------------
__global__ __launch_bounds__(64)
void conv1x1_kernel(const float* __restrict__ LW, const float* __restrict__ LB,
                    const float* __restrict__ SW, const float* __restrict__ SB,
                    float* __restrict__ out) {
    __shared__ float ws[54][64];
    int tid = threadIdx.x;
    int tx  = tid & 31, ty = tid >> 5;   // ty in {0,1} splits 54 channels 27/27
    int m0  = blockIdx.x * 64;           // 64 columns per block

    float accx[27], accy[27];
#pragma unroll
    for (int ch = 0; ch < 27; ch++) { accx[ch] = 0.f; accy[ch] = 0.f; }

    for (int c0 = 0; c0 < CIN; c0 += 64) {
        __syncthreads();
        for (int t = tid; t < 54 * 64; t += 64) {
            int ch = t >> 6, cc = t & 63;
            ws[ch][cc] = (ch < 36) ? LW[ch * CIN + c0 + cc]
                                   : SW[(ch - 36) * CIN + c0 + cc];
        }
        __syncthreads();
        for (int cc = 0; cc < 64; cc++) {
            float2 hv = *reinterpret_cast<const float2*>(
                &g_h[(size_t)(c0 + cc) * Mtot + m0 + tx * 2]);
#pragma unroll
            for (int ch = 0; ch < 27; ch++) {
                float w = ws[ty * 27 + ch][cc];
                accx[ch] = fmaf(w, hv.x, accx[ch]);
                accy[ch] = fmaf(w, hv.y, accy[ch]);
            }
        }
    }

#pragma unroll
    for (int ch = 0; ch < 27; ch++) {
        int gch = ty * 27 + ch;
#pragma unroll
        for (int e = 0; e < 2; e++) {
            int m = m0 + tx * 2 + e;
            int n = m >> 12, p = m & 4095;
            float v = e ? accy[ch] : accx[ch];
            if (gch < 36) {
                int a = gch >> 2, j = gch & 3;
                out[OFF_LOCS + ((size_t)n * NANCH + p * 9 + a) * 4 + j] = v + LB[gch];
            } else {
                int sch = gch - 36;
                int a = sch >> 1, j = sch & 1;
                out[OFF_SCORES + ((size_t)n * NANCH + p * 9 + a) * 2 + j] = v + SB[sch];
            }
        }
    }
}

// ---------------- decode + clip + size filter ----------------
__global__ void decode_kernel(const float* __restrict__ out,
                              const int* __restrict__ ihp, const int* __restrict__ iwp) {
    int gid = blockIdx.x * blockDim.x + threadIdx.x;
    if (gid >= NB * NANCH) return;
    int i = gid % NANCH;
    int a = i % 9;
    int p = i / 9;
    float sy = (float)((p >> 6) * 16);
    float sx = (float)((p & 63) * 16);
    float ay0 = sy + c_ba[a][0], ax0 = sx + c_ba[a][1];
    float ay1 = sy + c_ba[a][2], ax1 = sx + c_ba[a][3];
    float ah = ay1 - ay0, aw = ax1 - ax0;
    float acy = ay0 + 0.5f * ah, acx = ax0 + 0.5f * aw;

    float4 l = *(const float4*)&out[OFF_LOCS + (size_t)gid * 4];
    float cy = l.x * ah + acy;
    float cx = l.y * aw + acx;
    float hh = expf(l.z) * ah;
    float ww = expf(l.w) * aw;

    int vih = *ihp, viw = *iwp;
    float Hc = (vih > 0 && vih < 65536) ? (float)vih : __int_as_float(vih);
    float Wc = (viw > 0 && viw < 65536) ? (float)viw : __int_as_float(viw);

    float y0 = fminf(fmaxf(cy - 0.5f * hh, 0.f), Hc);
    float x0 = fminf(fmaxf(cx - 0.5f * ww, 0.f), Wc);
    float y1 = fminf(fmaxf(cy + 0.5f * hh, 0.f), Hc);
    float x1 = fminf(fmaxf(cx + 0.5f * ww, 0.f), Wc);

    *(float4*)&g_boxes[(size_t)gid * 4] = make_float4(y0, x0, y1, x1);
    float sc = out[OFF_SCORES + (size_t)gid * 2 + 1];
    g_fg[gid] = ((y1 - y0) >= 16.f && (x1 - x0) >= 16.f) ? sc : -INFINITY;
}

// ---------------- per-image exact top-2000 (radix select + bitonic sort) ----------------
__device__ __forceinline__ unsigned int fkey(float f) {
    unsigned int b = __float_as_uint(f);
    return (b & 0x80000000u) ? ~b : (b | 0x80000000u);
}

__global__ __launch_bounds__(1024)
void topk_kernel() {
    int n = blockIdx.x;
    const float* fg = g_fg + (size_t)n * NANCH;
    __shared__ unsigned int hist[256];
    __shared__ unsigned int sPref;
    __shared__ int sK, sCnt;
    __shared__ unsigned long long keys[4096];
    int tid = threadIdx.x;

    unsigned int pref = 0; int k = PRE_NMS;
    for (int pass = 0; pass < 4; pass++) {
        int shift = 24 - pass * 8;
        if (tid < 256) hist[tid] = 0u;
        __syncthreads();
        unsigned int mhi = pass ? (0xFFFFFFFFu << (shift + 8)) : 0u;
        for (int i = tid; i < NANCH; i += 1024) {
            unsigned int u = fkey(fg[i]);
            if ((u & mhi) == pref) atomicAdd(&hist[(u >> shift) & 255u], 1u);
        }
        __syncthreads();
        if (tid == 0) {
            int acc = 0, b = 255;
            for (; b > 0; b--) {
                if (acc + (int)hist[b] >= k) break;
                acc += (int)hist[b];
            }
            sPref = pref | ((unsigned)b << shift);
            sK = k - acc;
        }
        __syncthreads();
        pref = sPref; k = sK;
        __syncthreads();
    }
    unsigned int T = pref;
    if (tid == 0) sCnt = 0;
    __syncthreads();
    for (int i = tid; i < NANCH; i += 1024) {
        unsigned int u = fkey(fg[i]);
        if (u >= T) {
            int pos = atomicAdd(&sCnt, 1);
            if (pos < 4096)
                keys[pos] = ((unsigned long long)u << 32) | (unsigned)(0xFFFFFFFFu - (unsigned)i);
        }
    }
    __syncthreads();
    int cnt = sCnt < 4096 ? sCnt : 4096;
    for (int i = cnt + tid; i < 4096; i += 1024) keys[i] = 0ull;

    // bitonic sort, descending (ties: smaller original index first via ~i in low bits)
    for (int size = 2; size <= 4096; size <<= 1) {
        for (int stride = size >> 1; stride > 0; stride >>= 1) {
            __syncthreads();
            for (int t = tid; t < 2048; t += 1024) {
                int i = ((t & ~(stride - 1)) << 1) | (t & (stride - 1));
                int j = i | stride;
                unsigned long long ki = keys[i], kj = keys[j];
                bool descBlock = (i & size) == 0;
                if (descBlock ? (ki < kj) : (ki > kj)) { keys[i] = kj; keys[j] = ki; }
            }
        }
    }
    __syncthreads();

    for (int t = tid; t < PRE_NMS; t += 1024) {
        int idx = (int)(0xFFFFFFFFu - (unsigned int)(keys[t] & 0xFFFFFFFFull));
        float4 b4 = *(const float4*)&g_boxes[((size_t)n * NANCH + idx) * 4];
        *(float4*)&g_topbox[((size_t)n * PRE_NMS + t) * 4] = b4;
    }
}

// ---------------- pairwise IoU suppression bitmask ----------------
__global__ __launch_bounds__(64)
void iou_mask_kernel() {
    int n = blockIdx.z, rb = blockIdx.y, cb = blockIdx.x;
    int t = threadIdx.x;
    __shared__ float4 cbox[64];
    int col0 = cb * 64;
    cbox[t] = (col0 + t < PRE_NMS)
                  ? *(const float4*)&g_topbox[((size_t)n * PRE_NMS + col0 + t) * 4]
                  : make_float4(0, 0, 0, 0);
    __syncthreads();

    int row = rb * 64 + t;
    if (row >= PRE_NMS) return;
    float4 r4 = *(const float4*)&g_topbox[((size_t)n * PRE_NMS + row) * 4];
    float areaR = (r4.z - r4.x) * (r4.w - r4.y);
    unsigned long long bits = 0ull;
    int cmax = min(64, PRE_NMS - col0);
    for (int c = 0; c < cmax; c++) {
        int col = col0 + c;
        if (col <= row) continue;
        float4 c4 = cbox[c];
        float areaC = (c4.z - c4.x) * (c4.w - c4.y);
        float tly = fmaxf(r4.x, c4.x), tlx = fmaxf(r4.y, c4.y);
        float bry = fminf(r4.z, c4.z), brx = fminf(r4.w, c4.w);
        float ih = fmaxf(bry - tly, 0.f), iw = fmaxf(brx - tlx, 0.f);
        float inter = ih * iw;
        float iou = inter / (areaR + areaC - inter + 1e-9f);
        if (iou > 0.7f) bits |= (1ull << c);
    }
    g_mask[((size_t)n * PRE_NMS + row) * 32 + cb] = bits;
}

// ---------------- serial NMS scan + rois/roi_indices write ----------------
__global__ __launch_bounds__(32)
void nms_scan_kernel(float* __restrict__ out) {
    int n = blockIdx.x;
    int lane = threadIdx.x;
    __shared__ volatile unsigned long long rem[32];
    __shared__ int keep[POST_NMS];
    __shared__ volatile int cnt;
    rem[lane] = 0ull;
    if (lane == 0) cnt = 0;
    __syncwarp();

    for (int i = 0; i < PRE_NMS; i++) {
        bool sup = (rem[i >> 6] >> (i & 63)) & 1ull;
        if (!sup) {
            rem[lane] |= g_mask[((size_t)n * PRE_NMS + i) * 32 + lane];
            if (lane == 0) { keep[cnt] = i; cnt = cnt + 1; }
            __syncwarp();
            if (cnt >= POST_NMS) break;
        }
    }
    __syncwarp();
    int c = cnt;

    for (int k = lane; k < POST_NMS; k += 32) {
        float4 b = make_float4(0, 0, 0, 0);
        if (k < c) b = *(const float4*)&g_topbox[((size_t)n * PRE_NMS + keep[k]) * 4];
        *(float4*)&out[OFF_ROIS + ((size_t)n * POST_NMS + k) * 4] = b;
        out[OFF_IDX + (size_t)n * POST_NMS + k] = (float)n;
    }
}

// ---------------- launch ----------------
extern "C" void kernel_launch(void* const* d_in, const int* in_sizes, int n_in,
                              void* d_out, int out_size) {
    const float* x   = (const float*)d_in[0];
    const float* c1w = (const float*)d_in[1];
    const float* c1b = (const float*)d_in[2];
    const float* sw  = (const float*)d_in[3];
    const float* sb  = (const float*)d_in[4];
    const float* lw  = (const float*)d_in[5];
    const float* lb  = (const float*)d_in[6];
    const int*   ih  = (const int*)d_in[7];
    const int*   iw  = (const int*)d_in[8];
    float* out = (float*)d_out;

    wtrans_kernel<<<(COUT * KKtot + 255) / 256, 256>>>(c1w);
    conv1_kernel<<<dim3(256, 4), 256>>>(x, c1b);
    conv1x1_kernel<<<512, 64>>>(lw, lb, sw, sb, out);
    decode_kernel<<<(NB * NANCH + 255) / 256, 256>>>(out, ih, iw);
    topk_kernel<<<NB, 1024>>>();
    iou_mask_kernel<<<dim3(32, 32, NB), 64>>>();
    nms_scan_kernel<<<NB, 32>>>(out);
}

// round 3
// speedup vs baseline: 1.5898x; 1.5898x over previous
#include <cuda_runtime.h>
#include <math.h>

#define CIN    512
#define COUT   512
#define NB     8
#define HW     4096          // 64*64
#define Mtot   32768         // NB*HW
#define KKtot  4608          // CIN*9
#define NANCH  36864         // HW*9
#define PRE_NMS  2000
#define POST_NMS 300

#define OFF_LOCS   0
#define OFF_SCORES 1179648
#define OFF_ROIS   1769472
#define OFF_IDX    1779072

// ---------------- scratch (device globals; no allocs allowed) ----------------
__device__ float g_h[COUT * Mtot];                       // conv1 output, [cout][m]
__device__ float g_wt[COUT * KKtot];                     // weights re-laid out [k][rs*512+c]
__device__ float g_boxes[NB * NANCH * 4];
__device__ float g_fg[NB * NANCH];
__device__ float g_topbox[NB * PRE_NMS * 4];
__device__ unsigned long long g_mask[NB * PRE_NMS * 32]; // suppression bitmask

// packed f32x2 FMA: both halves are independent IEEE fp32 FMAs (bitwise == fmaf per lane)
__device__ __forceinline__ void ffma2(unsigned long long& d, unsigned long long a, unsigned long long b) {
    asm("fma.rn.f32x2 %0, %1, %2, %0;" : "+l"(d) : "l"(a), "l"(b));
}
__device__ __forceinline__ float f2lo(unsigned long long v) { return __uint_as_float((unsigned)(v & 0xFFFFFFFFull)); }
__device__ __forceinline__ float f2hi(unsigned long long v) { return __uint_as_float((unsigned)(v >> 32)); }

// base anchors (ymin,xmin,ymax,xmax), order: ratio-major, scale-minor (matches reference)
__constant__ float c_ba[9][4] = {
    { -37.254833995939045f,  -82.50966799187809f,   53.254833995939045f,  98.50966799187809f },
    { -82.50966799187809f,  -173.01933598375618f,   98.50966799187809f,  189.01933598375618f },
    { -173.01933598375618f, -354.03867196751236f,  189.01933598375618f,  370.03867196751236f },
    { -56.f,  -56.f,   72.f,   72.f },
    { -120.f, -120.f,  136.f,  136.f },
    { -248.f, -248.f,  264.f,  264.f },
    { -82.50966799187809f,   -37.254833995939045f,  98.50966799187809f,   53.254833995939045f },
    { -173.01933598375618f,  -82.50966799187809f,  189.01933598375618f,   98.50966799187809f },
    { -354.03867196751236f, -173.01933598375618f,  370.03867196751236f,  189.01933598375618f },
};

// ---------------- weight transpose: OIHW [k][c*9+rs] -> [k][rs*512+c] ----------------
__global__ void wtrans_kernel(const float* __restrict__ W) {
    int gid = blockIdx.x * blockDim.x + threadIdx.x;
    if (gid >= COUT * KKtot) return;
    int k  = gid / KKtot;
    int t  = gid - k * KKtot;
    int rs = t >> 9;          // 0..8
    int c  = t & 511;
    g_wt[gid] = W[(size_t)k * KKtot + c * 9 + rs];
}

// ---------------- conv1: 3x3 512->512 + bias + ReLU (implicit im2col SGEMM, FFMA2) ----------------
// K-order: rs outer (r ascending, s ascending), c inner ascending.
// Single accumulator chain per output => accumulation order = (r, s, c), identical to Round-1.
// Output-column pairing for f32x2: thread (tx) owns columns {2tx, 2tx+1} + p*32, p=0..3.
__global__ __launch_bounds__(256, 2)
void conv1_kernel(const float* __restrict__ X, const float* __restrict__ Bias) {
    __shared__ float2 As2[8][128];   // weights duplicated {a,a} for b64 broadcast loads
    __shared__ float  Bs[8][128];

    int bm  = blockIdx.x;           // 0..255  (m tile)
    int bk  = blockIdx.y;           // 0..3    (out-channel tile)
    int tid = threadIdx.x;
    int tx  = tid & 15, ty = tid >> 4;

    unsigned long long acc2[8][4];
#pragma unroll
    for (int i = 0; i < 8; i++)
#pragma unroll
        for (int p = 0; p < 4; p++) acc2[i][p] = 0ull;

    int a_i  = tid >> 1;            // 0..127
    int a_k4 = (tid & 1) * 4;       // 0 or 4
    const float* wrow = g_wt + (size_t)(bk * 128 + a_i) * KKtot + a_k4;
    int m0 = bm * 128;

    const int NSTEP = 9 * 64;       // 576 K-steps of depth 8

    // gather helper state (recomputed, cheap ALU)
    // element e: idx = tid + 256e; kk=idx>>7; j=idx&127
    // prefetch step 0
    float4 av = *reinterpret_cast<const float4*>(wrow);
    float  bv[4];
    {
        int rs = 0, dy = -1, dx = -1;
#pragma unroll
        for (int e = 0; e < 4; e++) {
            int idx = tid + 256 * e;
            int kk = idx >> 7, j = idx & 127;
            int m = m0 + j, n = m >> 12, p = m & 4095;
            int iy = (p >> 6) + dy, ix = (p & 63) + dx;
            int c  = kk;                    // c0 = 0
            float v = 0.f;
            if ((unsigned)iy < 64u && (unsigned)ix < 64u)
                v = X[(((size_t)n * CIN + c) << 12) + (iy << 6) + ix];
            bv[e] = v;
            (void)rs;
        }
    }

    for (int st = 0; st < NSTEP; st++) {
        __syncthreads();
        As2[a_k4 + 0][a_i] = make_float2(av.x, av.x);
        As2[a_k4 + 1][a_i] = make_float2(av.y, av.y);
        As2[a_k4 + 2][a_i] = make_float2(av.z, av.z);
        As2[a_k4 + 3][a_i] = make_float2(av.w, av.w);
#pragma unroll
        for (int e = 0; e < 4; e++) {
            int idx = tid + 256 * e;
            Bs[idx >> 7][idx & 127] = bv[e];
        }
        __syncthreads();

        // prefetch next step (overlaps with FMA below)
        if (st + 1 < NSTEP) {
            int stn = st + 1;
            av = *reinterpret_cast<const float4*>(wrow + stn * 8);
            int rs = stn >> 6;
            int c0 = (stn & 63) << 3;
            int r  = rs / 3, s = rs - 3 * r;
            int dy = r - 1, dx = s - 1;
#pragma unroll
            for (int e = 0; e < 4; e++) {
                int idx = tid + 256 * e;
                int kk = idx >> 7, j = idx & 127;
                int m = m0 + j, n = m >> 12, p = m & 4095;
                int iy = (p >> 6) + dy, ix = (p & 63) + dx;
                int c  = c0 + kk;
                float v = 0.f;
                if ((unsigned)iy < 64u && (unsigned)ix < 64u)
                    v = X[(((size_t)n * CIN + c) << 12) + (iy << 6) + ix];
                bv[e] = v;
            }
        }

#pragma unroll
        for (int kk = 0; kk < 8; kk++) {
            unsigned long long a2[8], b2[4];
#pragma unroll
            for (int i = 0; i < 8; i++)
                a2[i] = *reinterpret_cast<const unsigned long long*>(&As2[kk][ty * 8 + i]);
#pragma unroll
            for (int p = 0; p < 4; p++)
                b2[p] = *reinterpret_cast<const unsigned long long*>(&Bs[kk][tx * 2 + p * 32]);
#pragma unroll
            for (int i = 0; i < 8; i++)
#pragma unroll
                for (int p = 0; p < 4; p++)
                    ffma2(acc2[i][p], a2[i], b2[p]);
        }
    }

    // epilogue: bias + ReLU, write to g_h[k][m]
#pragma unroll
    for (int i = 0; i < 8; i++) {
        int ko = bk * 128 + ty * 8 + i;
        float bias = Bias[ko];
#pragma unroll
        for (int p = 0; p < 4; p++) {
            float2 v;
            v.x = fmaxf(f2lo(acc2[i][p]) + bias, 0.f);
            v.y = fmaxf(f2hi(acc2[i][p]) + bias, 0.f);
            *reinterpret_cast<float2*>(&g_h[(size_t)ko * Mtot + m0 + tx * 2 + p * 32]) = v;
        }
    }
}

// ---------------- 1x1 convs: 54 channels (36 loc + 18 score), FFMA2 over (m, m+1) pair ----------------
__global__ __launch_bounds__(64)
void conv1x1_kernel(const float* __restrict__ LW, const float* __restrict__ LB,
                    const float* __restrict__ SW, const float* __restrict__ SB,
                    float* __restrict__ out) {
    __shared__ float2 ws2[54][64];       // duplicated weights {w,w}
    int tid = threadIdx.x;
    int tx  = tid & 31, ty = tid >> 5;   // ty in {0,1} splits 54 channels 27/27
    int m0  = blockIdx.x * 64;           // 64 columns per block

    unsigned long long acc2[27];
#pragma unroll
    for (int ch = 0; ch < 27; ch++) acc2[ch] = 0ull;

    for (int c0 = 0; c0 < CIN; c0 += 64) {
        __syncthreads();
        for (int t = tid; t < 54 * 64; t += 64) {
            int ch = t >> 6, cc = t & 63;
            float w = (ch < 36) ? LW[ch * CIN + c0 + cc]
                                : SW[(ch - 36) * CIN + c0 + cc];
            ws2[ch][cc] = make_float2(w, w);
        }
        __syncthreads();
        for (int cc = 0; cc < 64; cc++) {
            unsigned long long hv = *reinterpret_cast<const unsigned long long*>(
                &g_h[(size_t)(c0 + cc) * Mtot + m0 + tx * 2]);
#pragma unroll
            for (int ch = 0; ch < 27; ch++) {
                unsigned long long w2 = *reinterpret_cast<const unsigned long long*>(
                    &ws2[ty * 27 + ch][cc]);
                ffma2(acc2[ch], w2, hv);
            }
        }
    }

#pragma unroll
    for (int ch = 0; ch < 27; ch++) {
        int gch = ty * 27 + ch;
#pragma unroll
        for (int e = 0; e < 2; e++) {
            int m = m0 + tx * 2 + e;
            int n = m >> 12, p = m & 4095;
            float v = e ? f2hi(acc2[ch]) : f2lo(acc2[ch]);
            if (gch < 36) {
                int a = gch >> 2, j = gch & 3;
                out[OFF_LOCS + ((size_t)n * NANCH + p * 9 + a) * 4 + j] = v + LB[gch];
            } else {
                int sch = gch - 36;
                int a = sch >> 1, j = sch & 1;
                out[OFF_SCORES + ((size_t)n * NANCH + p * 9 + a) * 2 + j] = v + SB[sch];
            }
        }
    }
}

// ---------------- decode + clip + size filter ----------------
__global__ void decode_kernel(const float* __restrict__ out,
                              const int* __restrict__ ihp, const int* __restrict__ iwp) {
    int gid = blockIdx.x * blockDim.x + threadIdx.x;
    if (gid >= NB * NANCH) return;
    int i = gid % NANCH;
    int a = i % 9;
    int p = i / 9;
    float sy = (float)((p >> 6) * 16);
    float sx = (float)((p & 63) * 16);
    float ay0 = sy + c_ba[a][0], ax0 = sx + c_ba[a][1];
    float ay1 = sy + c_ba[a][2], ax1 = sx + c_ba[a][3];
    float ah = ay1 - ay0, aw = ax1 - ax0;
    float acy = ay0 + 0.5f * ah, acx = ax0 + 0.5f * aw;

    float4 l = *(const float4*)&out[OFF_LOCS + (size_t)gid * 4];
    float cy = l.x * ah + acy;
    float cx = l.y * aw + acx;
    float hh = expf(l.z) * ah;
    float ww = expf(l.w) * aw;

    int vih = *ihp, viw = *iwp;
    float Hc = (vih > 0 && vih < 65536) ? (float)vih : __int_as_float(vih);
    float Wc = (viw > 0 && viw < 65536) ? (float)viw : __int_as_float(viw);

    float y0 = fminf(fmaxf(cy - 0.5f * hh, 0.f), Hc);
    float x0 = fminf(fmaxf(cx - 0.5f * ww, 0.f), Wc);
    float y1 = fminf(fmaxf(cy + 0.5f * hh, 0.f), Hc);
    float x1 = fminf(fmaxf(cx + 0.5f * ww, 0.f), Wc);

    *(float4*)&g_boxes[(size_t)gid * 4] = make_float4(y0, x0, y1, x1);
    float sc = out[OFF_SCORES + (size_t)gid * 2 + 1];
    g_fg[gid] = ((y1 - y0) >= 16.f && (x1 - x0) >= 16.f) ? sc : -INFINITY;
}

// ---------------- per-image exact top-2000 (radix select + bitonic sort) ----------------
__device__ __forceinline__ unsigned int fkey(float f) {
    unsigned int b = __float_as_uint(f);
    return (b & 0x80000000u) ? ~b : (b | 0x80000000u);
}

__global__ __launch_bounds__(1024)
void topk_kernel() {
    int n = blockIdx.x;
    const float* fg = g_fg + (size_t)n * NANCH;
    __shared__ unsigned int hist[256];
    __shared__ unsigned int sPref;
    __shared__ int sK, sCnt;
    __shared__ unsigned long long keys[4096];
    int tid = threadIdx.x;

    unsigned int pref = 0; int k = PRE_NMS;
    for (int pass = 0; pass < 4; pass++) {
        int shift = 24 - pass * 8;
        if (tid < 256) hist[tid] = 0u;
        __syncthreads();
        unsigned int mhi = pass ? (0xFFFFFFFFu << (shift + 8)) : 0u;
        for (int i = tid; i < NANCH; i += 1024) {
            unsigned int u = fkey(fg[i]);
            if ((u & mhi) == pref) atomicAdd(&hist[(u >> shift) & 255u], 1u);
        }
        __syncthreads();
        if (tid == 0) {
            int acc = 0, b = 255;
            for (; b > 0; b--) {
                if (acc + (int)hist[b] >= k) break;
                acc += (int)hist[b];
            }
            sPref = pref | ((unsigned)b << shift);
            sK = k - acc;
        }
        __syncthreads();
        pref = sPref; k = sK;
        __syncthreads();
    }
    unsigned int T = pref;
    if (tid == 0) sCnt = 0;
    __syncthreads();
    for (int i = tid; i < NANCH; i += 1024) {
        unsigned int u = fkey(fg[i]);
        if (u >= T) {
            int pos = atomicAdd(&sCnt, 1);
            if (pos < 4096)
                keys[pos] = ((unsigned long long)u << 32) | (unsigned)(0xFFFFFFFFu - (unsigned)i);
        }
    }
    __syncthreads();
    int cnt = sCnt < 4096 ? sCnt : 4096;
    for (int i = cnt + tid; i < 4096; i += 1024) keys[i] = 0ull;

    // bitonic sort, descending (ties: smaller original index first via ~i in low bits)
    for (int size = 2; size <= 4096; size <<= 1) {
        for (int stride = size >> 1; stride > 0; stride >>= 1) {
            __syncthreads();
            for (int t = tid; t < 2048; t += 1024) {
                int i = ((t & ~(stride - 1)) << 1) | (t & (stride - 1));
                int j = i | stride;
                unsigned long long ki = keys[i], kj = keys[j];
                bool descBlock = (i & size) == 0;
                if (descBlock ? (ki < kj) : (ki > kj)) { keys[i] = kj; keys[j] = ki; }
            }
        }
    }
    __syncthreads();

    for (int t = tid; t < PRE_NMS; t += 1024) {
        int idx = (int)(0xFFFFFFFFu - (unsigned int)(keys[t] & 0xFFFFFFFFull));
        float4 b4 = *(const float4*)&g_boxes[((size_t)n * NANCH + idx) * 4];
        *(float4*)&g_topbox[((size_t)n * PRE_NMS + t) * 4] = b4;
    }
}

// ---------------- pairwise IoU suppression bitmask ----------------
__global__ __launch_bounds__(64)
void iou_mask_kernel() {
    int n = blockIdx.z, rb = blockIdx.y, cb = blockIdx.x;
    int t = threadIdx.x;
    __shared__ float4 cbox[64];
    int col0 = cb * 64;
    cbox[t] = (col0 + t < PRE_NMS)
                  ? *(const float4*)&g_topbox[((size_t)n * PRE_NMS + col0 + t) * 4]
                  : make_float4(0, 0, 0, 0);
    __syncthreads();

    int row = rb * 64 + t;
    if (row >= PRE_NMS) return;
    float4 r4 = *(const float4*)&g_topbox[((size_t)n * PRE_NMS + row) * 4];
    float areaR = (r4.z - r4.x) * (r4.w - r4.y);
    unsigned long long bits = 0ull;
    int cmax = min(64, PRE_NMS - col0);
    for (int c = 0; c < cmax; c++) {
        int col = col0 + c;
        if (col <= row) continue;
        float4 c4 = cbox[c];
        float areaC = (c4.z - c4.x) * (c4.w - c4.y);
        float tly = fmaxf(r4.x, c4.x), tlx = fmaxf(r4.y, c4.y);
        float bry = fminf(r4.z, c4.z), brx = fminf(r4.w, c4.w);
        float ih = fmaxf(bry - tly, 0.f), iw = fmaxf(brx - tlx, 0.f);
        float inter = ih * iw;
        float iou = inter / (areaR + areaC - inter + 1e-9f);
        if (iou > 0.7f) bits |= (1ull << c);
    }
    g_mask[((size_t)n * PRE_NMS + row) * 32 + cb] = bits;
}

// ---------------- serial NMS scan + rois/roi_indices write ----------------
__global__ __launch_bounds__(32)
void nms_scan_kernel(float* __restrict__ out) {
    int n = blockIdx.x;
    int lane = threadIdx.x;
    __shared__ volatile unsigned long long rem[32];
    __shared__ int keep[POST_NMS];
    __shared__ volatile int cnt;
    rem[lane] = 0ull;
    if (lane == 0) cnt = 0;
    __syncwarp();

    for (int i = 0; i < PRE_NMS; i++) {
        bool sup = (rem[i >> 6] >> (i & 63)) & 1ull;
        if (!sup) {
            rem[lane] |= g_mask[((size_t)n * PRE_NMS + i) * 32 + lane];
            if (lane == 0) { keep[cnt] = i; cnt = cnt + 1; }
            __syncwarp();
            if (cnt >= POST_NMS) break;
        }
    }
    __syncwarp();
    int c = cnt;

    for (int k = lane; k < POST_NMS; k += 32) {
        float4 b = make_float4(0, 0, 0, 0);
        if (k < c) b = *(const float4*)&g_topbox[((size_t)n * PRE_NMS + keep[k]) * 4];
        *(float4*)&out[OFF_ROIS + ((size_t)n * POST_NMS + k) * 4] = b;
        out[OFF_IDX + (size_t)n * POST_NMS + k] = (float)n;
    }
}

// ---------------- launch ----------------
extern "C" void kernel_launch(void* const* d_in, const int* in_sizes, int n_in,
                              void* d_out, int out_size) {
    const float* x   = (const float*)d_in[0];
    const float* c1w = (const float*)d_in[1];
    const float* c1b = (const float*)d_in[2];
    const float* sw  = (const float*)d_in[3];
    const float* sb  = (const float*)d_in[4];
    const float* lw  = (const float*)d_in[5];
    const float* lb  = (const float*)d_in[6];
    const int*   ih  = (const int*)d_in[7];
    const int*   iw  = (const int*)d_in[8];
    float* out = (float*)d_out;

    wtrans_kernel<<<(COUT * KKtot + 255) / 256, 256>>>(c1w);
    conv1_kernel<<<dim3(256, 4), 256>>>(x, c1b);
    conv1x1_kernel<<<512, 64>>>(lw, lb, sw, sb, out);
    decode_kernel<<<(NB * NANCH + 255) / 256, 256>>>(out, ih, iw);
    topk_kernel<<<NB, 1024>>>();
    iou_mask_kernel<<<dim3(32, 32, NB), 64>>>();
    nms_scan_kernel<<<NB, 32>>>(out);
}

// round 4
// speedup vs baseline: 1.6937x; 1.0654x over previous
#include <cuda_runtime.h>
#include <math.h>

#define CIN    512
#define COUT   512
#define NB     8
#define HW     4096          // 64*64
#define Mtot   32768         // NB*HW
#define KKtot  4608          // CIN*9
#define NANCH  36864         // HW*9
#define PRE_NMS  2000
#define POST_NMS 300
#define NSTEP  576           // 9 taps * 64 c-blocks of depth 8

#define OFF_LOCS   0
#define OFF_SCORES 1179648
#define OFF_ROIS   1769472
#define OFF_IDX    1779072

// ---------------- scratch (device globals; no allocs allowed) ----------------
__device__ float g_h[COUT * Mtot];                       // conv1 output, [cout][m]
__device__ float g_wt[COUT * KKtot];                     // weights re-laid out [k][rs*512+c]
__device__ float g_boxes[NB * NANCH * 4];
__device__ float g_fg[NB * NANCH];
__device__ float g_topbox[NB * PRE_NMS * 4];
__device__ unsigned long long g_mask[NB * PRE_NMS * 32]; // suppression bitmask

// packed f32x2 FMA: both halves are independent IEEE fp32 FMAs (bitwise == fmaf per lane)
__device__ __forceinline__ void ffma2(unsigned long long& d, unsigned long long a, unsigned long long b) {
    asm("fma.rn.f32x2 %0, %1, %2, %0;" : "+l"(d) : "l"(a), "l"(b));
}
__device__ __forceinline__ float f2lo(unsigned long long v) { return __uint_as_float((unsigned)(v & 0xFFFFFFFFull)); }
__device__ __forceinline__ float f2hi(unsigned long long v) { return __uint_as_float((unsigned)(v >> 32)); }

// base anchors (ymin,xmin,ymax,xmax), order: ratio-major, scale-minor (matches reference)
__constant__ float c_ba[9][4] = {
    { -37.254833995939045f,  -82.50966799187809f,   53.254833995939045f,  98.50966799187809f },
    { -82.50966799187809f,  -173.01933598375618f,   98.50966799187809f,  189.01933598375618f },
    { -173.01933598375618f, -354.03867196751236f,  189.01933598375618f,  370.03867196751236f },
    { -56.f,  -56.f,   72.f,   72.f },
    { -120.f, -120.f,  136.f,  136.f },
    { -248.f, -248.f,  264.f,  264.f },
    { -82.50966799187809f,   -37.254833995939045f,  98.50966799187809f,   53.254833995939045f },
    { -173.01933598375618f,  -82.50966799187809f,  189.01933598375618f,   98.50966799187809f },
    { -354.03867196751236f, -173.01933598375618f,  370.03867196751236f,  189.01933598375618f },
};

// ---------------- weight transpose: OIHW [k][c*9+rs] -> [k][rs*512+c] ----------------
__global__ void wtrans_kernel(const float* __restrict__ W) {
    int gid = blockIdx.x * blockDim.x + threadIdx.x;
    if (gid >= COUT * KKtot) return;
    int k  = gid / KKtot;
    int t  = gid - k * KKtot;
    int rs = t >> 9;          // 0..8
    int c  = t & 511;
    g_wt[gid] = W[(size_t)k * KKtot + c * 9 + rs];
}

// ---------------- conv1: 3x3 512->512 + bias + ReLU (implicit im2col SGEMM, FFMA2) ----------------
// K-order: rs outer (r asc, s asc), c inner asc, depth-8 stages. One chain per output.
// Thread owns 8 rows x 8 cols; cols = {4tx..4tx+3} and {4tx+64..4tx+67}.
__global__ __launch_bounds__(256, 2)
void conv1_kernel(const float* __restrict__ X, const float* __restrict__ Bias) {
    __shared__ float2 As2[2][8][128];   // weights duplicated {a,a}
    __shared__ float  Bs[2][8][128];

    int bm  = blockIdx.x;           // 0..255  (m tile)
    int bk  = blockIdx.y;           // 0..3    (out-channel tile)
    int tid = threadIdx.x;
    int tx  = tid & 15, ty = tid >> 4;

    unsigned long long acc2[8][4];
#pragma unroll
    for (int i = 0; i < 8; i++)
#pragma unroll
        for (int p = 0; p < 4; p++) acc2[i][p] = 0ull;

    int a_i  = tid >> 1;            // 0..127
    int a_k4 = (tid & 1) * 4;       // 0 or 4
    const float* wrow = g_wt + (size_t)(bk * 128 + a_i) * KKtot + a_k4;
    int m0 = bm * 128;

    // per-thread fixed gather decomposition (element e: idx = tid + 256e)
    int e_kk[4], e_j[4], e_n[4], e_y[4], e_x[4];
#pragma unroll
    for (int e = 0; e < 4; e++) {
        int idx = tid + 256 * e;
        e_kk[e] = idx >> 7;
        e_j[e]  = idx & 127;
        int m   = m0 + e_j[e];
        e_n[e]  = m >> 12;
        int p   = m & 4095;
        e_y[e]  = p >> 6;
        e_x[e]  = p & 63;
    }

    // per-rs gather state
    const float* pbase[4];
    bool pval[4];
#define SETUP_RS(RS) do {                                                     \
        int r_ = (RS) / 3, s_ = (RS) - 3 * r_;                                \
        int dy_ = r_ - 1, dx_ = s_ - 1;                                       \
        _Pragma("unroll")                                                     \
        for (int e = 0; e < 4; e++) {                                         \
            int iy = e_y[e] + dy_, ix = e_x[e] + dx_;                         \
            pval[e]  = ((unsigned)iy < 64u) && ((unsigned)ix < 64u);          \
            pbase[e] = X + (((size_t)e_n[e] * CIN + e_kk[e]) << 12)           \
                         + (iy << 6) + ix;                                    \
        }                                                                     \
    } while (0)

    float4 av;
    float  bv[4];

    // prefetch stage 0 and store into buffer 0
    SETUP_RS(0);
    av = *reinterpret_cast<const float4*>(wrow);
#pragma unroll
    for (int e = 0; e < 4; e++) bv[e] = pval[e] ? pbase[e][0] : 0.f;

    As2[0][a_k4 + 0][a_i] = make_float2(av.x, av.x);
    As2[0][a_k4 + 1][a_i] = make_float2(av.y, av.y);
    As2[0][a_k4 + 2][a_i] = make_float2(av.z, av.z);
    As2[0][a_k4 + 3][a_i] = make_float2(av.w, av.w);
#pragma unroll
    for (int e = 0; e < 4; e++) Bs[0][e_kk[e]][e_j[e]] = bv[e];
    __syncthreads();

    for (int st = 0; st < NSTEP; st++) {
        int cur = st & 1;
        int stn = st + 1;
        bool havenext = stn < NSTEP;

        // prefetch next stage into registers (hidden under the FMA loop)
        if (havenext) {
            if ((stn & 63) == 0) SETUP_RS(stn >> 6);
            av = *reinterpret_cast<const float4*>(wrow + stn * 8);
            size_t off = (size_t)(stn & 63) << 15;   // cb * 8 * 4096 floats
#pragma unroll
            for (int e = 0; e < 4; e++) bv[e] = pval[e] ? pbase[e][off] : 0.f;
        }

        // FMA on current buffer
#pragma unroll
        for (int kk = 0; kk < 8; kk++) {
            ulonglong2 aq0 = *reinterpret_cast<const ulonglong2*>(&As2[cur][kk][ty * 8 + 0]);
            ulonglong2 aq1 = *reinterpret_cast<const ulonglong2*>(&As2[cur][kk][ty * 8 + 2]);
            ulonglong2 aq2 = *reinterpret_cast<const ulonglong2*>(&As2[cur][kk][ty * 8 + 4]);
            ulonglong2 aq3 = *reinterpret_cast<const ulonglong2*>(&As2[cur][kk][ty * 8 + 6]);
            ulonglong2 bq0 = *reinterpret_cast<const ulonglong2*>(&Bs[cur][kk][tx * 4]);
            ulonglong2 bq1 = *reinterpret_cast<const ulonglong2*>(&Bs[cur][kk][tx * 4 + 64]);
            unsigned long long a2[8] = { aq0.x, aq0.y, aq1.x, aq1.y, aq2.x, aq2.y, aq3.x, aq3.y };
            unsigned long long b2[4] = { bq0.x, bq0.y, bq1.x, bq1.y };
#pragma unroll
            for (int i = 0; i < 8; i++)
#pragma unroll
                for (int p = 0; p < 4; p++)
                    ffma2(acc2[i][p], a2[i], b2[p]);
        }

        // store prefetched stage into the other buffer
        if (havenext) {
            int nb = stn & 1;
            As2[nb][a_k4 + 0][a_i] = make_float2(av.x, av.x);
            As2[nb][a_k4 + 1][a_i] = make_float2(av.y, av.y);
            As2[nb][a_k4 + 2][a_i] = make_float2(av.z, av.z);
            As2[nb][a_k4 + 3][a_i] = make_float2(av.w, av.w);
#pragma unroll
            for (int e = 0; e < 4; e++) Bs[nb][e_kk[e]][e_j[e]] = bv[e];
        }
        __syncthreads();
    }
#undef SETUP_RS

    // epilogue: bias + ReLU, write to g_h[k][m] as float4
#pragma unroll
    for (int i = 0; i < 8; i++) {
        int ko = bk * 128 + ty * 8 + i;
        float bias = Bias[ko];
#pragma unroll
        for (int h = 0; h < 2; h++) {
            float4 v;
            v.x = fmaxf(f2lo(acc2[i][h * 2 + 0]) + bias, 0.f);
            v.y = fmaxf(f2hi(acc2[i][h * 2 + 0]) + bias, 0.f);
            v.z = fmaxf(f2lo(acc2[i][h * 2 + 1]) + bias, 0.f);
            v.w = fmaxf(f2hi(acc2[i][h * 2 + 1]) + bias, 0.f);
            *reinterpret_cast<float4*>(&g_h[(size_t)ko * Mtot + m0 + tx * 4 + h * 64]) = v;
        }
    }
}

// ---------------- 1x1 convs: 54 channels (36 loc + 18 score), FFMA2 over (m, m+1) pair ----------------
__global__ __launch_bounds__(64)
void conv1x1_kernel(const float* __restrict__ LW, const float* __restrict__ LB,
                    const float* __restrict__ SW, const float* __restrict__ SB,
                    float* __restrict__ out) {
    __shared__ float2 ws2[54][64];       // duplicated weights {w,w}
    int tid = threadIdx.x;
    int tx  = tid & 31, ty = tid >> 5;   // ty in {0,1} splits 54 channels 27/27
    int m0  = blockIdx.x * 64;           // 64 columns per block

    unsigned long long acc2[27];
#pragma unroll
    for (int ch = 0; ch < 27; ch++) acc2[ch] = 0ull;

    for (int c0 = 0; c0 < CIN; c0 += 64) {
        __syncthreads();
        for (int t = tid; t < 54 * 64; t += 64) {
            int ch = t >> 6, cc = t & 63;
            float w = (ch < 36) ? LW[ch * CIN + c0 + cc]
                                : SW[(ch - 36) * CIN + c0 + cc];
            ws2[ch][cc] = make_float2(w, w);
        }
        __syncthreads();
        for (int cc = 0; cc < 64; cc++) {
            unsigned long long hv = *reinterpret_cast<const unsigned long long*>(
                &g_h[(size_t)(c0 + cc) * Mtot + m0 + tx * 2]);
#pragma unroll
            for (int ch = 0; ch < 27; ch++) {
                unsigned long long w2 = *reinterpret_cast<const unsigned long long*>(
                    &ws2[ty * 27 + ch][cc]);
                ffma2(acc2[ch], w2, hv);
            }
        }
    }

#pragma unroll
    for (int ch = 0; ch < 27; ch++) {
        int gch = ty * 27 + ch;
#pragma unroll
        for (int e = 0; e < 2; e++) {
            int m = m0 + tx * 2 + e;
            int n = m >> 12, p = m & 4095;
            float v = e ? f2hi(acc2[ch]) : f2lo(acc2[ch]);
            if (gch < 36) {
                int a = gch >> 2, j = gch & 3;
                out[OFF_LOCS + ((size_t)n * NANCH + p * 9 + a) * 4 + j] = v + LB[gch];
            } else {
                int sch = gch - 36;
                int a = sch >> 1, j = sch & 1;
                out[OFF_SCORES + ((size_t)n * NANCH + p * 9 + a) * 2 + j] = v + SB[sch];
            }
        }
    }
}

// ---------------- decode + clip + size filter ----------------
__global__ void decode_kernel(const float* __restrict__ out,
                              const int* __restrict__ ihp, const int* __restrict__ iwp) {
    int gid = blockIdx.x * blockDim.x + threadIdx.x;
    if (gid >= NB * NANCH) return;
    int i = gid % NANCH;
    int a = i % 9;
    int p = i / 9;
    float sy = (float)((p >> 6) * 16);
    float sx = (float)((p & 63) * 16);
    float ay0 = sy + c_ba[a][0], ax0 = sx + c_ba[a][1];
    float ay1 = sy + c_ba[a][2], ax1 = sx + c_ba[a][3];
    float ah = ay1 - ay0, aw = ax1 - ax0;
    float acy = ay0 + 0.5f * ah, acx = ax0 + 0.5f * aw;

    float4 l = *(const float4*)&out[OFF_LOCS + (size_t)gid * 4];
    float cy = l.x * ah + acy;
    float cx = l.y * aw + acx;
    float hh = expf(l.z) * ah;
    float ww = expf(l.w) * aw;

    int vih = *ihp, viw = *iwp;
    float Hc = (vih > 0 && vih < 65536) ? (float)vih : __int_as_float(vih);
    float Wc = (viw > 0 && viw < 65536) ? (float)viw : __int_as_float(viw);

    float y0 = fminf(fmaxf(cy - 0.5f * hh, 0.f), Hc);
    float x0 = fminf(fmaxf(cx - 0.5f * ww, 0.f), Wc);
    float y1 = fminf(fmaxf(cy + 0.5f * hh, 0.f), Hc);
    float x1 = fminf(fmaxf(cx + 0.5f * ww, 0.f), Wc);

    *(float4*)&g_boxes[(size_t)gid * 4] = make_float4(y0, x0, y1, x1);
    float sc = out[OFF_SCORES + (size_t)gid * 2 + 1];
    g_fg[gid] = ((y1 - y0) >= 16.f && (x1 - x0) >= 16.f) ? sc : -INFINITY;
}

// ---------------- per-image exact top-2000 (radix select + bitonic sort) ----------------
__device__ __forceinline__ unsigned int fkey(float f) {
    unsigned int b = __float_as_uint(f);
    return (b & 0x80000000u) ? ~b : (b | 0x80000000u);
}

__global__ __launch_bounds__(1024)
void topk_kernel() {
    int n = blockIdx.x;
    const float* fg = g_fg + (size_t)n * NANCH;
    __shared__ unsigned int hist[256];
    __shared__ unsigned int sPref;
    __shared__ int sK, sCnt;
    __shared__ unsigned long long keys[4096];
    int tid = threadIdx.x;

    unsigned int pref = 0; int k = PRE_NMS;
    for (int pass = 0; pass < 4; pass++) {
        int shift = 24 - pass * 8;
        if (tid < 256) hist[tid] = 0u;
        __syncthreads();
        unsigned int mhi = pass ? (0xFFFFFFFFu << (shift + 8)) : 0u;
        for (int i = tid; i < NANCH; i += 1024) {
            unsigned int u = fkey(fg[i]);
            if ((u & mhi) == pref) atomicAdd(&hist[(u >> shift) & 255u], 1u);
        }
        __syncthreads();
        if (tid == 0) {
            int acc = 0, b = 255;
            for (; b > 0; b--) {
                if (acc + (int)hist[b] >= k) break;
                acc += (int)hist[b];
            }
            sPref = pref | ((unsigned)b << shift);
            sK = k - acc;
        }
        __syncthreads();
        pref = sPref; k = sK;
        __syncthreads();
    }
    unsigned int T = pref;
    if (tid == 0) sCnt = 0;
    __syncthreads();
    for (int i = tid; i < NANCH; i += 1024) {
        unsigned int u = fkey(fg[i]);
        if (u >= T) {
            int pos = atomicAdd(&sCnt, 1);
            if (pos < 4096)
                keys[pos] = ((unsigned long long)u << 32) | (unsigned)(0xFFFFFFFFu - (unsigned)i);
        }
    }
    __syncthreads();
    int cnt = sCnt < 4096 ? sCnt : 4096;
    for (int i = cnt + tid; i < 4096; i += 1024) keys[i] = 0ull;

    // bitonic sort, descending (ties: smaller original index first via ~i in low bits)
    for (int size = 2; size <= 4096; size <<= 1) {
        for (int stride = size >> 1; stride > 0; stride >>= 1) {
            __syncthreads();
            for (int t = tid; t < 2048; t += 1024) {
                int i = ((t & ~(stride - 1)) << 1) | (t & (stride - 1));
                int j = i | stride;
                unsigned long long ki = keys[i], kj = keys[j];
                bool descBlock = (i & size) == 0;
                if (descBlock ? (ki < kj) : (ki > kj)) { keys[i] = kj; keys[j] = ki; }
            }
        }
    }
    __syncthreads();

    for (int t = tid; t < PRE_NMS; t += 1024) {
        int idx = (int)(0xFFFFFFFFu - (unsigned int)(keys[t] & 0xFFFFFFFFull));
        float4 b4 = *(const float4*)&g_boxes[((size_t)n * NANCH + idx) * 4];
        *(float4*)&g_topbox[((size_t)n * PRE_NMS + t) * 4] = b4;
    }
}

// ---------------- pairwise IoU suppression bitmask ----------------
__global__ __launch_bounds__(64)
void iou_mask_kernel() {
    int n = blockIdx.z, rb = blockIdx.y, cb = blockIdx.x;
    int t = threadIdx.x;
    __shared__ float4 cbox[64];
    int col0 = cb * 64;
    cbox[t] = (col0 + t < PRE_NMS)
                  ? *(const float4*)&g_topbox[((size_t)n * PRE_NMS + col0 + t) * 4]
                  : make_float4(0, 0, 0, 0);
    __syncthreads();

    int row = rb * 64 + t;
    if (row >= PRE_NMS) return;
    float4 r4 = *(const float4*)&g_topbox[((size_t)n * PRE_NMS + row) * 4];
    float areaR = (r4.z - r4.x) * (r4.w - r4.y);
    unsigned long long bits = 0ull;
    int cmax = min(64, PRE_NMS - col0);
    for (int c = 0; c < cmax; c++) {
        int col = col0 + c;
        if (col <= row) continue;
        float4 c4 = cbox[c];
        float areaC = (c4.z - c4.x) * (c4.w - c4.y);
        float tly = fmaxf(r4.x, c4.x), tlx = fmaxf(r4.y, c4.y);
        float bry = fminf(r4.z, c4.z), brx = fminf(r4.w, c4.w);
        float ih = fmaxf(bry - tly, 0.f), iw = fmaxf(brx - tlx, 0.f);
        float inter = ih * iw;
        float iou = inter / (areaR + areaC - inter + 1e-9f);
        if (iou > 0.7f) bits |= (1ull << c);
    }
    g_mask[((size_t)n * PRE_NMS + row) * 32 + cb] = bits;
}

// ---------------- serial NMS scan + rois/roi_indices write ----------------
__global__ __launch_bounds__(32)
void nms_scan_kernel(float* __restrict__ out) {
    int n = blockIdx.x;
    int lane = threadIdx.x;
    __shared__ volatile unsigned long long rem[32];
    __shared__ int keep[POST_NMS];
    __shared__ volatile int cnt;
    rem[lane] = 0ull;
    if (lane == 0) cnt = 0;
    __syncwarp();

    for (int i = 0; i < PRE_NMS; i++) {
        bool sup = (rem[i >> 6] >> (i & 63)) & 1ull;
        if (!sup) {
            rem[lane] |= g_mask[((size_t)n * PRE_NMS + i) * 32 + lane];
            if (lane == 0) { keep[cnt] = i; cnt = cnt + 1; }
            __syncwarp();
            if (cnt >= POST_NMS) break;
        }
    }
    __syncwarp();
    int c = cnt;

    for (int k = lane; k < POST_NMS; k += 32) {
        float4 b = make_float4(0, 0, 0, 0);
        if (k < c) b = *(const float4*)&g_topbox[((size_t)n * PRE_NMS + keep[k]) * 4];
        *(float4*)&out[OFF_ROIS + ((size_t)n * POST_NMS + k) * 4] = b;
        out[OFF_IDX + (size_t)n * POST_NMS + k] = (float)n;
    }
}

// ---------------- launch ----------------
extern "C" void kernel_launch(void* const* d_in, const int* in_sizes, int n_in,
                              void* d_out, int out_size) {
    const float* x   = (const float*)d_in[0];
    const float* c1w = (const float*)d_in[1];
    const float* c1b = (const float*)d_in[2];
    const float* sw  = (const float*)d_in[3];
    const float* sb  = (const float*)d_in[4];
    const float* lw  = (const float*)d_in[5];
    const float* lb  = (const float*)d_in[6];
    const int*   ih  = (const int*)d_in[7];
    const int*   iw  = (const int*)d_in[8];
    float* out = (float*)d_out;

    wtrans_kernel<<<(COUT * KKtot + 255) / 256, 256>>>(c1w);
    conv1_kernel<<<dim3(256, 4), 256>>>(x, c1b);
    conv1x1_kernel<<<512, 64>>>(lw, lb, sw, sb, out);
    decode_kernel<<<(NB * NANCH + 255) / 256, 256>>>(out, ih, iw);
    topk_kernel<<<NB, 1024>>>();
    iou_mask_kernel<<<dim3(32, 32, NB), 64>>>();
    nms_scan_kernel<<<NB, 32>>>(out);
}

// round 5
// speedup vs baseline: 1.7613x; 1.0399x over previous
#include <cuda_runtime.h>
#include <math.h>

#define CIN    512
#define COUT   512
#define NB     8
#define HW     4096          // 64*64
#define Mtot   32768         // NB*HW
#define KKtot  4608          // CIN*9
#define NANCH  36864         // HW*9
#define PRE_NMS  2000
#define POST_NMS 300
#define DEPTH  16
#define NSTEP  288           // 9 taps * 32 c-blocks of depth 16
#define PADW   66
#define PADA   4356          // 66*66
#define CBSTRIDE 69696       // 16 channels * 4356 floats per c-block in g_xpad

#define OFF_LOCS   0
#define OFF_SCORES 1179648
#define OFF_ROIS   1769472
#define OFF_IDX    1779072

// ---------------- scratch (device globals; no allocs allowed) ----------------
__device__ float g_h[COUT * Mtot];                       // conv1 output, [cout][m]
__device__ float g_wt[COUT * KKtot];                     // weights re-laid out [k][rs*512+c]
__device__ float g_xpad[NB * CIN * PADA];                // zero-padded input, [n][c][66][66]
__device__ float g_boxes[NB * NANCH * 4];
__device__ float g_fg[NB * NANCH];
__device__ float g_topbox[NB * PRE_NMS * 4];
__device__ unsigned long long g_mask[NB * PRE_NMS * 32]; // suppression bitmask

// packed f32x2 FMA: both halves are independent IEEE fp32 FMAs (bitwise == fmaf per lane)
__device__ __forceinline__ void ffma2(unsigned long long& d, unsigned long long a, unsigned long long b) {
    asm("fma.rn.f32x2 %0, %1, %2, %0;" : "+l"(d) : "l"(a), "l"(b));
}
__device__ __forceinline__ float f2lo(unsigned long long v) { return __uint_as_float((unsigned)(v & 0xFFFFFFFFull)); }
__device__ __forceinline__ float f2hi(unsigned long long v) { return __uint_as_float((unsigned)(v >> 32)); }

// base anchors (ymin,xmin,ymax,xmax), order: ratio-major, scale-minor (matches reference)
__constant__ float c_ba[9][4] = {
    { -37.254833995939045f,  -82.50966799187809f,   53.254833995939045f,  98.50966799187809f },
    { -82.50966799187809f,  -173.01933598375618f,   98.50966799187809f,  189.01933598375618f },
    { -173.01933598375618f, -354.03867196751236f,  189.01933598375618f,  370.03867196751236f },
    { -56.f,  -56.f,   72.f,   72.f },
    { -120.f, -120.f,  136.f,  136.f },
    { -248.f, -248.f,  264.f,  264.f },
    { -82.50966799187809f,   -37.254833995939045f,  98.50966799187809f,   53.254833995939045f },
    { -173.01933598375618f,  -82.50966799187809f,  189.01933598375618f,   98.50966799187809f },
    { -354.03867196751236f, -173.01933598375618f,  370.03867196751236f,  189.01933598375618f },
};

// ---------------- weight transpose: OIHW [k][c*9+rs] -> [k][rs*512+c] ----------------
__global__ void wtrans_kernel(const float* __restrict__ W) {
    int gid = blockIdx.x * blockDim.x + threadIdx.x;
    if (gid >= COUT * KKtot) return;
    int k  = gid / KKtot;
    int t  = gid - k * KKtot;
    int rs = t >> 9;          // 0..8
    int c  = t & 511;
    g_wt[gid] = W[(size_t)k * KKtot + c * 9 + rs];
}

// ---------------- input halo padding: X[n][c][64][64] -> g_xpad[n][c][66][66] ----------------
__global__ void xpad_kernel(const float* __restrict__ X) {
    int plane = blockIdx.y;                      // 0..4095  (n*512 + c)
    int e = blockIdx.x * blockDim.x + threadIdx.x;
    if (e >= PADA) return;
    int iy = e / PADW, ix = e - iy * PADW;
    float v = 0.f;
    if (iy >= 1 && iy <= 64 && ix >= 1 && ix <= 64)
        v = X[((size_t)plane << 12) + ((iy - 1) << 6) + (ix - 1)];
    g_xpad[(size_t)plane * PADA + e] = v;
}

// ---------------- conv1: 3x3 512->512 + bias + ReLU (implicit im2col SGEMM, FFMA2) ----------------
// K-order: rs outer (r asc, s asc), c inner asc, depth-16 stages. One chain per output.
// Thread owns 8 rows x 8 cols; cols = {4tx..4tx+3} and {4tx+64..4tx+67}.
__global__ __launch_bounds__(256, 2)
void conv1_kernel(const float* __restrict__ Bias) {
    __shared__ float2 As2[2][DEPTH][128];   // weights duplicated {a,a}   32KB
    __shared__ float  Bs[2][DEPTH][128];    //                            16KB

    int bm  = blockIdx.x;           // 0..255  (m tile)
    int bk  = blockIdx.y;           // 0..3    (out-channel tile)
    int tid = threadIdx.x;
    int tx  = tid & 15, ty = tid >> 4;

    unsigned long long acc2[8][4];
#pragma unroll
    for (int i = 0; i < 8; i++)
#pragma unroll
        for (int p = 0; p < 4; p++) acc2[i][p] = 0ull;

    int a_i  = tid >> 1;            // 0..127
    int a_k8 = (tid & 1) * 8;       // 0 or 8
    const float* wrow = g_wt + (size_t)(bk * 128 + a_i) * KKtot + a_k8;
    int m0 = bm * 128;

    // per-thread fixed gather bases (element e: idx = tid + 256e, e=0..7)
    // base_e = index of (n, c=e_kk, iy=e_y+1, ix=e_x+1) in g_xpad (center tap, c-block 0)
    int e_kk[8], e_j[8];
    int base_e[8];
#pragma unroll
    for (int e = 0; e < 8; e++) {
        int idx = tid + 256 * e;
        e_kk[e] = idx >> 7;         // 0..15
        e_j[e]  = idx & 127;
        int m   = m0 + e_j[e];
        int n   = m >> 12;
        int p   = m & 4095;
        int yy  = p >> 6, xx = p & 63;
        base_e[e] = (n * CIN + e_kk[e]) * PADA + (yy + 1) * PADW + (xx + 1);
    }

    float4 av0, av1;
    float  bv[8];

    // prefetch stage 0 (rs=0 => dy=-1,dx=-1 => delta = -66-1 = -67; cb=0)
    av0 = *reinterpret_cast<const float4*>(wrow);
    av1 = *reinterpret_cast<const float4*>(wrow + 4);
#pragma unroll
    for (int e = 0; e < 8; e++) bv[e] = g_xpad[base_e[e] - 67];

    // stage into buffer 0
#pragma unroll
    for (int q = 0; q < 4; q++) {
        float a = (&av0.x)[q];
        As2[0][a_k8 + q][a_i] = make_float2(a, a);
    }
#pragma unroll
    for (int q = 0; q < 4; q++) {
        float a = (&av1.x)[q];
        As2[0][a_k8 + 4 + q][a_i] = make_float2(a, a);
    }
#pragma unroll
    for (int e = 0; e < 8; e++) Bs[0][e_kk[e]][e_j[e]] = bv[e];
    __syncthreads();

    for (int st = 0; st < NSTEP; st++) {
        int cur = st & 1;
        int stn = st + 1;
        bool havenext = stn < NSTEP;

        // prefetch next stage into registers (hidden under the FMA loop)
        if (havenext) {
            av0 = *reinterpret_cast<const float4*>(wrow + stn * DEPTH);
            av1 = *reinterpret_cast<const float4*>(wrow + stn * DEPTH + 4);
            int rs = stn >> 5, cb = stn & 31;
            int r  = rs / 3, s = rs - 3 * r;
            int c_off = (r - 1) * PADW + (s - 1) + cb * CBSTRIDE;
#pragma unroll
            for (int e = 0; e < 8; e++) bv[e] = g_xpad[base_e[e] + c_off];
        }

        // FMA on current buffer
#pragma unroll
        for (int kk = 0; kk < DEPTH; kk++) {
            ulonglong2 aq0 = *reinterpret_cast<const ulonglong2*>(&As2[cur][kk][ty * 8 + 0]);
            ulonglong2 aq1 = *reinterpret_cast<const ulonglong2*>(&As2[cur][kk][ty * 8 + 2]);
            ulonglong2 aq2 = *reinterpret_cast<const ulonglong2*>(&As2[cur][kk][ty * 8 + 4]);
            ulonglong2 aq3 = *reinterpret_cast<const ulonglong2*>(&As2[cur][kk][ty * 8 + 6]);
            ulonglong2 bq0 = *reinterpret_cast<const ulonglong2*>(&Bs[cur][kk][tx * 4]);
            ulonglong2 bq1 = *reinterpret_cast<const ulonglong2*>(&Bs[cur][kk][tx * 4 + 64]);
            unsigned long long a2[8] = { aq0.x, aq0.y, aq1.x, aq1.y, aq2.x, aq2.y, aq3.x, aq3.y };
            unsigned long long b2[4] = { bq0.x, bq0.y, bq1.x, bq1.y };
#pragma unroll
            for (int i = 0; i < 8; i++)
#pragma unroll
                for (int p = 0; p < 4; p++)
                    ffma2(acc2[i][p], a2[i], b2[p]);
        }

        // store prefetched stage into the other buffer
        if (havenext) {
            int nb = stn & 1;
#pragma unroll
            for (int q = 0; q < 4; q++) {
                float a = (&av0.x)[q];
                As2[nb][a_k8 + q][a_i] = make_float2(a, a);
            }
#pragma unroll
            for (int q = 0; q < 4; q++) {
                float a = (&av1.x)[q];
                As2[nb][a_k8 + 4 + q][a_i] = make_float2(a, a);
            }
#pragma unroll
            for (int e = 0; e < 8; e++) Bs[nb][e_kk[e]][e_j[e]] = bv[e];
        }
        __syncthreads();
    }

    // epilogue: bias + ReLU, write to g_h[k][m] as float4
#pragma unroll
    for (int i = 0; i < 8; i++) {
        int ko = bk * 128 + ty * 8 + i;
        float bias = Bias[ko];
#pragma unroll
        for (int h = 0; h < 2; h++) {
            float4 v;
            v.x = fmaxf(f2lo(acc2[i][h * 2 + 0]) + bias, 0.f);
            v.y = fmaxf(f2hi(acc2[i][h * 2 + 0]) + bias, 0.f);
            v.z = fmaxf(f2lo(acc2[i][h * 2 + 1]) + bias, 0.f);
            v.w = fmaxf(f2hi(acc2[i][h * 2 + 1]) + bias, 0.f);
            *reinterpret_cast<float4*>(&g_h[(size_t)ko * Mtot + m0 + tx * 4 + h * 64]) = v;
        }
    }
}

// ---------------- 1x1 convs: 54 channels (36 loc + 18 score), FFMA2, 4 cols/thread ----------------
// ty in 0..3 owns 14 channels (gch = ty*14+ch; gch 54,55 are zero-weight dummies, stores skipped)
__global__ __launch_bounds__(128)
void conv1x1_kernel(const float* __restrict__ LW, const float* __restrict__ LB,
                    const float* __restrict__ SW, const float* __restrict__ SB,
                    float* __restrict__ out) {
    __shared__ float2 ws2[56][64];       // duplicated weights {w,w}, 28KB
    int tid = threadIdx.x;
    int tx  = tid & 31, ty = tid >> 5;   // ty 0..3
    int m0  = blockIdx.x * 128;          // 128 columns per block

    unsigned long long acc2[14][2];
#pragma unroll
    for (int ch = 0; ch < 14; ch++) { acc2[ch][0] = 0ull; acc2[ch][1] = 0ull; }

    for (int c0 = 0; c0 < CIN; c0 += 64) {
        __syncthreads();
        for (int t = tid; t < 56 * 64; t += 128) {
            int ch = t >> 6, cc = t & 63;
            float w = 0.f;
            if (ch < 36)      w = LW[ch * CIN + c0 + cc];
            else if (ch < 54) w = SW[(ch - 36) * CIN + c0 + cc];
            ws2[ch][cc] = make_float2(w, w);
        }
        __syncthreads();
        for (int cc = 0; cc < 64; cc++) {
            ulonglong2 hq = *reinterpret_cast<const ulonglong2*>(
                &g_h[(size_t)(c0 + cc) * Mtot + m0 + tx * 4]);
#pragma unroll
            for (int ch = 0; ch < 14; ch++) {
                unsigned long long w2 = *reinterpret_cast<const unsigned long long*>(
                    &ws2[ty * 14 + ch][cc]);
                ffma2(acc2[ch][0], w2, hq.x);
                ffma2(acc2[ch][1], w2, hq.y);
            }
        }
    }

#pragma unroll
    for (int ch = 0; ch < 14; ch++) {
        int gch = ty * 14 + ch;
        if (gch >= 54) continue;
#pragma unroll
        for (int e = 0; e < 4; e++) {
            int m = m0 + tx * 4 + e;
            int n = m >> 12, p = m & 4095;
            unsigned long long a = acc2[ch][e >> 1];
            float v = (e & 1) ? f2hi(a) : f2lo(a);
            if (gch < 36) {
                int an = gch >> 2, j = gch & 3;
                out[OFF_LOCS + ((size_t)n * NANCH + p * 9 + an) * 4 + j] = v + LB[gch];
            } else {
                int sch = gch - 36;
                int an = sch >> 1, j = sch & 1;
                out[OFF_SCORES + ((size_t)n * NANCH + p * 9 + an) * 2 + j] = v + SB[sch];
            }
        }
    }
}

// ---------------- decode + clip + size filter ----------------
__global__ void decode_kernel(const float* __restrict__ out,
                              const int* __restrict__ ihp, const int* __restrict__ iwp) {
    int gid = blockIdx.x * blockDim.x + threadIdx.x;
    if (gid >= NB * NANCH) return;
    int i = gid % NANCH;
    int a = i % 9;
    int p = i / 9;
    float sy = (float)((p >> 6) * 16);
    float sx = (float)((p & 63) * 16);
    float ay0 = sy + c_ba[a][0], ax0 = sx + c_ba[a][1];
    float ay1 = sy + c_ba[a][2], ax1 = sx + c_ba[a][3];
    float ah = ay1 - ay0, aw = ax1 - ax0;
    float acy = ay0 + 0.5f * ah, acx = ax0 + 0.5f * aw;

    float4 l = *(const float4*)&out[OFF_LOCS + (size_t)gid * 4];
    float cy = l.x * ah + acy;
    float cx = l.y * aw + acx;
    float hh = expf(l.z) * ah;
    float ww = expf(l.w) * aw;

    int vih = *ihp, viw = *iwp;
    float Hc = (vih > 0 && vih < 65536) ? (float)vih : __int_as_float(vih);
    float Wc = (viw > 0 && viw < 65536) ? (float)viw : __int_as_float(viw);

    float y0 = fminf(fmaxf(cy - 0.5f * hh, 0.f), Hc);
    float x0 = fminf(fmaxf(cx - 0.5f * ww, 0.f), Wc);
    float y1 = fminf(fmaxf(cy + 0.5f * hh, 0.f), Hc);
    float x1 = fminf(fmaxf(cx + 0.5f * ww, 0.f), Wc);

    *(float4*)&g_boxes[(size_t)gid * 4] = make_float4(y0, x0, y1, x1);
    float sc = out[OFF_SCORES + (size_t)gid * 2 + 1];
    g_fg[gid] = ((y1 - y0) >= 16.f && (x1 - x0) >= 16.f) ? sc : -INFINITY;
}

// ---------------- per-image exact top-2000 (radix select + bitonic sort) ----------------
__device__ __forceinline__ unsigned int fkey(float f) {
    unsigned int b = __float_as_uint(f);
    return (b & 0x80000000u) ? ~b : (b | 0x80000000u);
}

__global__ __launch_bounds__(1024)
void topk_kernel() {
    int n = blockIdx.x;
    const float* fg = g_fg + (size_t)n * NANCH;
    __shared__ unsigned int hist[256];
    __shared__ unsigned int sPref;
    __shared__ int sK, sCnt;
    __shared__ unsigned long long keys[4096];
    int tid = threadIdx.x;

    unsigned int pref = 0; int k = PRE_NMS;
    for (int pass = 0; pass < 4; pass++) {
        int shift = 24 - pass * 8;
        if (tid < 256) hist[tid] = 0u;
        __syncthreads();
        unsigned int mhi = pass ? (0xFFFFFFFFu << (shift + 8)) : 0u;
        for (int i = tid; i < NANCH; i += 1024) {
            unsigned int u = fkey(fg[i]);
            if ((u & mhi) == pref) atomicAdd(&hist[(u >> shift) & 255u], 1u);
        }
        __syncthreads();
        if (tid == 0) {
            int acc = 0, b = 255;
            for (; b > 0; b--) {
                if (acc + (int)hist[b] >= k) break;
                acc += (int)hist[b];
            }
            sPref = pref | ((unsigned)b << shift);
            sK = k - acc;
        }
        __syncthreads();
        pref = sPref; k = sK;
        __syncthreads();
    }
    unsigned int T = pref;
    if (tid == 0) sCnt = 0;
    __syncthreads();
    for (int i = tid; i < NANCH; i += 1024) {
        unsigned int u = fkey(fg[i]);
        if (u >= T) {
            int pos = atomicAdd(&sCnt, 1);
            if (pos < 4096)
                keys[pos] = ((unsigned long long)u << 32) | (unsigned)(0xFFFFFFFFu - (unsigned)i);
        }
    }
    __syncthreads();
    int cnt = sCnt < 4096 ? sCnt : 4096;
    for (int i = cnt + tid; i < 4096; i += 1024) keys[i] = 0ull;

    // bitonic sort, descending (ties: smaller original index first via ~i in low bits)
    for (int size = 2; size <= 4096; size <<= 1) {
        for (int stride = size >> 1; stride > 0; stride >>= 1) {
            __syncthreads();
            for (int t = tid; t < 2048; t += 1024) {
                int i = ((t & ~(stride - 1)) << 1) | (t & (stride - 1));
                int j = i | stride;
                unsigned long long ki = keys[i], kj = keys[j];
                bool descBlock = (i & size) == 0;
                if (descBlock ? (ki < kj) : (ki > kj)) { keys[i] = kj; keys[j] = ki; }
            }
        }
    }
    __syncthreads();

    for (int t = tid; t < PRE_NMS; t += 1024) {
        int idx = (int)(0xFFFFFFFFu - (unsigned int)(keys[t] & 0xFFFFFFFFull));
        float4 b4 = *(const float4*)&g_boxes[((size_t)n * NANCH + idx) * 4];
        *(float4*)&g_topbox[((size_t)n * PRE_NMS + t) * 4] = b4;
    }
}

// ---------------- pairwise IoU suppression bitmask ----------------
__global__ __launch_bounds__(64)
void iou_mask_kernel() {
    int n = blockIdx.z, rb = blockIdx.y, cb = blockIdx.x;
    int t = threadIdx.x;
    __shared__ float4 cbox[64];
    int col0 = cb * 64;
    cbox[t] = (col0 + t < PRE_NMS)
                  ? *(const float4*)&g_topbox[((size_t)n * PRE_NMS + col0 + t) * 4]
                  : make_float4(0, 0, 0, 0);
    __syncthreads();

    int row = rb * 64 + t;
    if (row >= PRE_NMS) return;
    float4 r4 = *(const float4*)&g_topbox[((size_t)n * PRE_NMS + row) * 4];
    float areaR = (r4.z - r4.x) * (r4.w - r4.y);
    unsigned long long bits = 0ull;
    int cmax = min(64, PRE_NMS - col0);
    for (int c = 0; c < cmax; c++) {
        int col = col0 + c;
        if (col <= row) continue;
        float4 c4 = cbox[c];
        float areaC = (c4.z - c4.x) * (c4.w - c4.y);
        float tly = fmaxf(r4.x, c4.x), tlx = fmaxf(r4.y, c4.y);
        float bry = fminf(r4.z, c4.z), brx = fminf(r4.w, c4.w);
        float ih = fmaxf(bry - tly, 0.f), iw = fmaxf(brx - tlx, 0.f);
        float inter = ih * iw;
        float iou = inter / (areaR + areaC - inter + 1e-9f);
        if (iou > 0.7f) bits |= (1ull << c);
    }
    g_mask[((size_t)n * PRE_NMS + row) * 32 + cb] = bits;
}

// ---------------- serial NMS scan + rois/roi_indices write ----------------
__global__ __launch_bounds__(32)
void nms_scan_kernel(float* __restrict__ out) {
    int n = blockIdx.x;
    int lane = threadIdx.x;
    __shared__ volatile unsigned long long rem[32];
    __shared__ int keep[POST_NMS];
    __shared__ volatile int cnt;
    rem[lane] = 0ull;
    if (lane == 0) cnt = 0;
    __syncwarp();

    for (int i = 0; i < PRE_NMS; i++) {
        bool sup = (rem[i >> 6] >> (i & 63)) & 1ull;
        if (!sup) {
            rem[lane] |= g_mask[((size_t)n * PRE_NMS + i) * 32 + lane];
            if (lane == 0) { keep[cnt] = i; cnt = cnt + 1; }
            __syncwarp();
            if (cnt >= POST_NMS) break;
        }
    }
    __syncwarp();
    int c = cnt;

    for (int k = lane; k < POST_NMS; k += 32) {
        float4 b = make_float4(0, 0, 0, 0);
        if (k < c) b = *(const float4*)&g_topbox[((size_t)n * PRE_NMS + keep[k]) * 4];
        *(float4*)&out[OFF_ROIS + ((size_t)n * POST_NMS + k) * 4] = b;
        out[OFF_IDX + (size_t)n * POST_NMS + k] = (float)n;
    }
}

// ---------------- launch ----------------
extern "C" void kernel_launch(void* const* d_in, const int* in_sizes, int n_in,
                              void* d_out, int out_size) {
    const float* x   = (const float*)d_in[0];
    const float* c1w = (const float*)d_in[1];
    const float* c1b = (const float*)d_in[2];
    const float* sw  = (const float*)d_in[3];
    const float* sb  = (const float*)d_in[4];
    const float* lw  = (const float*)d_in[5];
    const float* lb  = (const float*)d_in[6];
    const int*   ih  = (const int*)d_in[7];
    const int*   iw  = (const int*)d_in[8];
    float* out = (float*)d_out;

    wtrans_kernel<<<(COUT * KKtot + 255) / 256, 256>>>(c1w);
    xpad_kernel<<<dim3((PADA + 255) / 256, NB * CIN), 256>>>(x);
    conv1_kernel<<<dim3(256, 4), 256>>>(c1b);
    conv1x1_kernel<<<256, 128>>>(lw, lb, sw, sb, out);
    decode_kernel<<<(NB * NANCH + 255) / 256, 256>>>(out, ih, iw);
    topk_kernel<<<NB, 1024>>>();
    iou_mask_kernel<<<dim3(32, 32, NB), 64>>>();
    nms_scan_kernel<<<NB, 32>>>(out);
}

// round 6
// speedup vs baseline: 1.8180x; 1.0322x over previous
#include <cuda_runtime.h>
#include <math.h>

#define CIN    512
#define COUT   512
#define NB     8
#define HW     4096          // 64*64
#define Mtot   32768         // NB*HW
#define KKtot  4608          // CIN*9
#define NANCH  36864         // HW*9
#define PRE_NMS  2000
#define POST_NMS 300
#define DEPTH  16
#define NSTEP  288           // 9 taps * 32 c-blocks of depth 16
#define PADW   66
#define PADA   4356          // 66*66
#define CBSTRIDE 69696       // 16 channels * 4356 floats per c-block in g_xpad

#define OFF_LOCS   0
#define OFF_SCORES 1179648
#define OFF_ROIS   1769472
#define OFF_IDX    1779072

// ---------------- scratch (device globals; no allocs allowed) ----------------
__device__ float g_h[COUT * Mtot];                       // conv1 output, [cout][m]
__device__ float g_wt[COUT * KKtot];                     // weights re-laid out [k][rs*512+c]
__device__ float g_xpad[NB * CIN * PADA];                // zero-padded input, [n][c][66][66]
__device__ float g_boxes[NB * NANCH * 4];
__device__ float g_fg[NB * NANCH];
__device__ float g_topbox[NB * PRE_NMS * 4];
__device__ unsigned long long g_mask[NB * PRE_NMS * 32]; // suppression bitmask

// packed f32x2 FMA: both halves are independent IEEE fp32 FMAs (bitwise == fmaf per lane)
__device__ __forceinline__ void ffma2(unsigned long long& d, unsigned long long a, unsigned long long b) {
    asm("fma.rn.f32x2 %0, %1, %2, %0;" : "+l"(d) : "l"(a), "l"(b));
}
__device__ __forceinline__ float f2lo(unsigned long long v) { return __uint_as_float((unsigned)(v & 0xFFFFFFFFull)); }
__device__ __forceinline__ float f2hi(unsigned long long v) { return __uint_as_float((unsigned)(v >> 32)); }

// base anchors (ymin,xmin,ymax,xmax), order: ratio-major, scale-minor (matches reference)
__constant__ float c_ba[9][4] = {
    { -37.254833995939045f,  -82.50966799187809f,   53.254833995939045f,  98.50966799187809f },
    { -82.50966799187809f,  -173.01933598375618f,   98.50966799187809f,  189.01933598375618f },
    { -173.01933598375618f, -354.03867196751236f,  189.01933598375618f,  370.03867196751236f },
    { -56.f,  -56.f,   72.f,   72.f },
    { -120.f, -120.f,  136.f,  136.f },
    { -248.f, -248.f,  264.f,  264.f },
    { -82.50966799187809f,   -37.254833995939045f,  98.50966799187809f,   53.254833995939045f },
    { -173.01933598375618f,  -82.50966799187809f,  189.01933598375618f,   98.50966799187809f },
    { -354.03867196751236f, -173.01933598375618f,  370.03867196751236f,  189.01933598375618f },
};

// ---------------- weight transpose: OIHW [k][c*9+rs] -> [k][rs*512+c] ----------------
__global__ void wtrans_kernel(const float* __restrict__ W) {
    int gid = blockIdx.x * blockDim.x + threadIdx.x;
    if (gid >= COUT * KKtot) return;
    int k  = gid / KKtot;
    int t  = gid - k * KKtot;
    int rs = t >> 9;          // 0..8
    int c  = t & 511;
    g_wt[gid] = W[(size_t)k * KKtot + c * 9 + rs];
}

// ---------------- input halo padding: X[n][c][64][64] -> g_xpad[n][c][66][66] ----------------
__global__ void xpad_kernel(const float* __restrict__ X) {
    int plane = blockIdx.y;                      // 0..4095  (n*512 + c)
    int e = blockIdx.x * blockDim.x + threadIdx.x;
    if (e >= PADA) return;
    int iy = e / PADW, ix = e - iy * PADW;
    float v = 0.f;
    if (iy >= 1 && iy <= 64 && ix >= 1 && ix <= 64)
        v = X[((size_t)plane << 12) + ((iy - 1) << 6) + (ix - 1)];
    g_xpad[(size_t)plane * PADA + e] = v;
}

// ---------------- conv1: 3x3 512->512 + bias + ReLU (implicit im2col SGEMM, FFMA2) ----------------
// K-order: rs outer (r asc, s asc), c inner asc, depth-16 stages. One chain per output.
// Thread owns 8 rows x 8 cols; cols = {4tx..4tx+3} and {4tx+64..4tx+67}.
// Grid (4, 256): bk fastest so 4 consecutive CTAs share the same im2col B tile (L2 reuse).
__global__ __launch_bounds__(256, 2)
void conv1_kernel(const float* __restrict__ Bias) {
    __shared__ float2 As2[2][DEPTH][128];   // weights duplicated {a,a}   32KB
    __shared__ float  Bs[2][DEPTH][128];    //                            16KB

    int bk  = blockIdx.x;           // 0..3    (out-channel tile)
    int bm  = blockIdx.y;           // 0..255  (m tile)
    int tid = threadIdx.x;
    int tx  = tid & 15, ty = tid >> 4;

    unsigned long long acc2[8][4];
#pragma unroll
    for (int i = 0; i < 8; i++)
#pragma unroll
        for (int p = 0; p < 4; p++) acc2[i][p] = 0ull;

    int a_i  = tid >> 1;            // 0..127
    int a_k8 = (tid & 1) * 8;       // 0 or 8
    const float* wrow = g_wt + (size_t)(bk * 128 + a_i) * KKtot + a_k8;
    int m0 = bm * 128;

    // per-thread fixed gather bases (element e: idx = tid + 256e, e=0..7)
    int e_kk[8], e_j[8];
    int base_e[8];
#pragma unroll
    for (int e = 0; e < 8; e++) {
        int idx = tid + 256 * e;
        e_kk[e] = idx >> 7;         // 0..15
        e_j[e]  = idx & 127;
        int m   = m0 + e_j[e];
        int n   = m >> 12;
        int p   = m & 4095;
        int yy  = p >> 6, xx = p & 63;
        base_e[e] = (n * CIN + e_kk[e]) * PADA + (yy + 1) * PADW + (xx + 1);
    }

    float4 av0, av1;
    float  bv[8];

    // prefetch stage 0 (rs=0 => dy=-1,dx=-1 => delta = -67; cb=0)
    av0 = *reinterpret_cast<const float4*>(wrow);
    av1 = *reinterpret_cast<const float4*>(wrow + 4);
#pragma unroll
    for (int e = 0; e < 8; e++) bv[e] = g_xpad[base_e[e] - 67];

#pragma unroll
    for (int q = 0; q < 4; q++) {
        float a = (&av0.x)[q];
        As2[0][a_k8 + q][a_i] = make_float2(a, a);
    }
#pragma unroll
    for (int q = 0; q < 4; q++) {
        float a = (&av1.x)[q];
        As2[0][a_k8 + 4 + q][a_i] = make_float2(a, a);
    }
#pragma unroll
    for (int e = 0; e < 8; e++) Bs[0][e_kk[e]][e_j[e]] = bv[e];
    __syncthreads();

    for (int st = 0; st < NSTEP; st++) {
        int cur = st & 1;
        int stn = st + 1;
        bool havenext = stn < NSTEP;

        // prefetch next stage into registers (hidden under the FMA loop)
        if (havenext) {
            av0 = *reinterpret_cast<const float4*>(wrow + stn * DEPTH);
            av1 = *reinterpret_cast<const float4*>(wrow + stn * DEPTH + 4);
            int rs = stn >> 5, cb = stn & 31;
            int r  = rs / 3, s = rs - 3 * r;
            int c_off = (r - 1) * PADW + (s - 1) + cb * CBSTRIDE;
#pragma unroll
            for (int e = 0; e < 8; e++) bv[e] = g_xpad[base_e[e] + c_off];
        }

        // FMA on current buffer
#pragma unroll
        for (int kk = 0; kk < DEPTH; kk++) {
            ulonglong2 aq0 = *reinterpret_cast<const ulonglong2*>(&As2[cur][kk][ty * 8 + 0]);
            ulonglong2 aq1 = *reinterpret_cast<const ulonglong2*>(&As2[cur][kk][ty * 8 + 2]);
            ulonglong2 aq2 = *reinterpret_cast<const ulonglong2*>(&As2[cur][kk][ty * 8 + 4]);
            ulonglong2 aq3 = *reinterpret_cast<const ulonglong2*>(&As2[cur][kk][ty * 8 + 6]);
            ulonglong2 bq0 = *reinterpret_cast<const ulonglong2*>(&Bs[cur][kk][tx * 4]);
            ulonglong2 bq1 = *reinterpret_cast<const ulonglong2*>(&Bs[cur][kk][tx * 4 + 64]);
            unsigned long long a2[8] = { aq0.x, aq0.y, aq1.x, aq1.y, aq2.x, aq2.y, aq3.x, aq3.y };
            unsigned long long b2[4] = { bq0.x, bq0.y, bq1.x, bq1.y };
#pragma unroll
            for (int i = 0; i < 8; i++)
#pragma unroll
                for (int p = 0; p < 4; p++)
                    ffma2(acc2[i][p], a2[i], b2[p]);
        }

        // store prefetched stage into the other buffer
        if (havenext) {
            int nb = stn & 1;
#pragma unroll
            for (int q = 0; q < 4; q++) {
                float a = (&av0.x)[q];
                As2[nb][a_k8 + q][a_i] = make_float2(a, a);
            }
#pragma unroll
            for (int q = 0; q < 4; q++) {
                float a = (&av1.x)[q];
                As2[nb][a_k8 + 4 + q][a_i] = make_float2(a, a);
            }
#pragma unroll
            for (int e = 0; e < 8; e++) Bs[nb][e_kk[e]][e_j[e]] = bv[e];
        }
        __syncthreads();
    }

    // epilogue: bias + ReLU, write to g_h[k][m] as float4
#pragma unroll
    for (int i = 0; i < 8; i++) {
        int ko = bk * 128 + ty * 8 + i;
        float bias = Bias[ko];
#pragma unroll
        for (int h = 0; h < 2; h++) {
            float4 v;
            v.x = fmaxf(f2lo(acc2[i][h * 2 + 0]) + bias, 0.f);
            v.y = fmaxf(f2hi(acc2[i][h * 2 + 0]) + bias, 0.f);
            v.z = fmaxf(f2lo(acc2[i][h * 2 + 1]) + bias, 0.f);
            v.w = fmaxf(f2hi(acc2[i][h * 2 + 1]) + bias, 0.f);
            *reinterpret_cast<float4*>(&g_h[(size_t)ko * Mtot + m0 + tx * 4 + h * 64]) = v;
        }
    }
}

// ---------------- 1x1 convs: 54 channels (36 loc + 18 score), FFMA2, latency-hidden ----------------
// 512 blocks x 256 threads. ty in 0..7 owns 7 channels (gch = ty*7+ch; 54,55 dummies).
// tx owns 2 adjacent columns (even/odd pair -> same f32x2 pairing, chains ascending-c).
__global__ __launch_bounds__(256)
void conv1x1_kernel(const float* __restrict__ LW, const float* __restrict__ LB,
                    const float* __restrict__ SW, const float* __restrict__ SB,
                    float* __restrict__ out) {
    __shared__ float2 ws2[56][64];       // duplicated weights {w,w}, 28KB
    int tid = threadIdx.x;
    int tx  = tid & 31, ty = tid >> 5;   // ty 0..7
    int m0  = blockIdx.x * 64;           // 64 columns per block

    unsigned long long acc2[7];
#pragma unroll
    for (int ch = 0; ch < 7; ch++) acc2[ch] = 0ull;

    for (int c0 = 0; c0 < CIN; c0 += 64) {
        __syncthreads();
        for (int t = tid; t < 56 * 64; t += 256) {
            int ch = t >> 6, cc = t & 63;
            float w = 0.f;
            if (ch < 36)      w = LW[ch * CIN + c0 + cc];
            else if (ch < 54) w = SW[(ch - 36) * CIN + c0 + cc];
            ws2[ch][cc] = make_float2(w, w);
        }
        __syncthreads();
        for (int cc = 0; cc < 64; cc++) {
            unsigned long long hv = *reinterpret_cast<const unsigned long long*>(
                &g_h[(size_t)(c0 + cc) * Mtot + m0 + tx * 2]);
#pragma unroll
            for (int ch = 0; ch < 7; ch++) {
                unsigned long long w2 = *reinterpret_cast<const unsigned long long*>(
                    &ws2[ty * 7 + ch][cc]);
                ffma2(acc2[ch], w2, hv);
            }
        }
    }

#pragma unroll
    for (int ch = 0; ch < 7; ch++) {
        int gch = ty * 7 + ch;
        if (gch >= 54) continue;
#pragma unroll
        for (int e = 0; e < 2; e++) {
            int m = m0 + tx * 2 + e;
            int n = m >> 12, p = m & 4095;
            float v = e ? f2hi(acc2[ch]) : f2lo(acc2[ch]);
            if (gch < 36) {
                int an = gch >> 2, j = gch & 3;
                out[OFF_LOCS + ((size_t)n * NANCH + p * 9 + an) * 4 + j] = v + LB[gch];
            } else {
                int sch = gch - 36;
                int an = sch >> 1, j = sch & 1;
                out[OFF_SCORES + ((size_t)n * NANCH + p * 9 + an) * 2 + j] = v + SB[sch];
            }
        }
    }
}

// ---------------- decode + clip + size filter ----------------
__global__ void decode_kernel(const float* __restrict__ out,
                              const int* __restrict__ ihp, const int* __restrict__ iwp) {
    int gid = blockIdx.x * blockDim.x + threadIdx.x;
    if (gid >= NB * NANCH) return;
    int i = gid % NANCH;
    int a = i % 9;
    int p = i / 9;
    float sy = (float)((p >> 6) * 16);
    float sx = (float)((p & 63) * 16);
    float ay0 = sy + c_ba[a][0], ax0 = sx + c_ba[a][1];
    float ay1 = sy + c_ba[a][2], ax1 = sx + c_ba[a][3];
    float ah = ay1 - ay0, aw = ax1 - ax0;
    float acy = ay0 + 0.5f * ah, acx = ax0 + 0.5f * aw;

    float4 l = *(const float4*)&out[OFF_LOCS + (size_t)gid * 4];
    float cy = l.x * ah + acy;
    float cx = l.y * aw + acx;
    float hh = expf(l.z) * ah;
    float ww = expf(l.w) * aw;

    int vih = *ihp, viw = *iwp;
    float Hc = (vih > 0 && vih < 65536) ? (float)vih : __int_as_float(vih);
    float Wc = (viw > 0 && viw < 65536) ? (float)viw : __int_as_float(viw);

    float y0 = fminf(fmaxf(cy - 0.5f * hh, 0.f), Hc);
    float x0 = fminf(fmaxf(cx - 0.5f * ww, 0.f), Wc);
    float y1 = fminf(fmaxf(cy + 0.5f * hh, 0.f), Hc);
    float x1 = fminf(fmaxf(cx + 0.5f * ww, 0.f), Wc);

    *(float4*)&g_boxes[(size_t)gid * 4] = make_float4(y0, x0, y1, x1);
    float sc = out[OFF_SCORES + (size_t)gid * 2 + 1];
    g_fg[gid] = ((y1 - y0) >= 16.f && (x1 - x0) >= 16.f) ? sc : -INFINITY;
}

// ---------------- per-image exact top-2000 (radix select + bitonic sort) ----------------
__device__ __forceinline__ unsigned int fkey(float f) {
    unsigned int b = __float_as_uint(f);
    return (b & 0x80000000u) ? ~b : (b | 0x80000000u);
}

__global__ __launch_bounds__(1024)
void topk_kernel() {
    int n = blockIdx.x;
    const float* fg = g_fg + (size_t)n * NANCH;
    __shared__ unsigned int hist[256];
    __shared__ unsigned int sPref;
    __shared__ int sK, sCnt;
    __shared__ unsigned long long keys[4096];
    int tid = threadIdx.x;

    unsigned int pref = 0; int k = PRE_NMS;
    for (int pass = 0; pass < 4; pass++) {
        int shift = 24 - pass * 8;
        if (tid < 256) hist[tid] = 0u;
        __syncthreads();
        unsigned int mhi = pass ? (0xFFFFFFFFu << (shift + 8)) : 0u;
        for (int i = tid; i < NANCH; i += 1024) {
            unsigned int u = fkey(fg[i]);
            if ((u & mhi) == pref) atomicAdd(&hist[(u >> shift) & 255u], 1u);
        }
        __syncthreads();
        if (tid == 0) {
            int acc = 0, b = 255;
            for (; b > 0; b--) {
                if (acc + (int)hist[b] >= k) break;
                acc += (int)hist[b];
            }
            sPref = pref | ((unsigned)b << shift);
            sK = k - acc;
        }
        __syncthreads();
        pref = sPref; k = sK;
        __syncthreads();
    }
    unsigned int T = pref;
    if (tid == 0) sCnt = 0;
    __syncthreads();
    for (int i = tid; i < NANCH; i += 1024) {
        unsigned int u = fkey(fg[i]);
        if (u >= T) {
            int pos = atomicAdd(&sCnt, 1);
            if (pos < 4096)
                keys[pos] = ((unsigned long long)u << 32) | (unsigned)(0xFFFFFFFFu - (unsigned)i);
        }
    }
    __syncthreads();
    int cnt = sCnt < 4096 ? sCnt : 4096;
    for (int i = cnt + tid; i < 4096; i += 1024) keys[i] = 0ull;

    // bitonic sort, descending (ties: smaller original index first via ~i in low bits)
    for (int size = 2; size <= 4096; size <<= 1) {
        for (int stride = size >> 1; stride > 0; stride >>= 1) {
            __syncthreads();
            for (int t = tid; t < 2048; t += 1024) {
                int i = ((t & ~(stride - 1)) << 1) | (t & (stride - 1));
                int j = i | stride;
                unsigned long long ki = keys[i], kj = keys[j];
                bool descBlock = (i & size) == 0;
                if (descBlock ? (ki < kj) : (ki > kj)) { keys[i] = kj; keys[j] = ki; }
            }
        }
    }
    __syncthreads();

    for (int t = tid; t < PRE_NMS; t += 1024) {
        int idx = (int)(0xFFFFFFFFu - (unsigned int)(keys[t] & 0xFFFFFFFFull));
        float4 b4 = *(const float4*)&g_boxes[((size_t)n * NANCH + idx) * 4];
        *(float4*)&g_topbox[((size_t)n * PRE_NMS + t) * 4] = b4;
    }
}

// ---------------- pairwise IoU suppression bitmask ----------------
__global__ __launch_bounds__(64)
void iou_mask_kernel() {
    int n = blockIdx.z, rb = blockIdx.y, cb = blockIdx.x;
    int t = threadIdx.x;
    __shared__ float4 cbox[64];
    int col0 = cb * 64;
    cbox[t] = (col0 + t < PRE_NMS)
                  ? *(const float4*)&g_topbox[((size_t)n * PRE_NMS + col0 + t) * 4]
                  : make_float4(0, 0, 0, 0);
    __syncthreads();

    int row = rb * 64 + t;
    if (row >= PRE_NMS) return;
    float4 r4 = *(const float4*)&g_topbox[((size_t)n * PRE_NMS + row) * 4];
    float areaR = (r4.z - r4.x) * (r4.w - r4.y);
    unsigned long long bits = 0ull;
    int cmax = min(64, PRE_NMS - col0);
    for (int c = 0; c < cmax; c++) {
        int col = col0 + c;
        if (col <= row) continue;
        float4 c4 = cbox[c];
        float areaC = (c4.z - c4.x) * (c4.w - c4.y);
        float tly = fmaxf(r4.x, c4.x), tlx = fmaxf(r4.y, c4.y);
        float bry = fminf(r4.z, c4.z), brx = fminf(r4.w, c4.w);
        float ih = fmaxf(bry - tly, 0.f), iw = fmaxf(brx - tlx, 0.f);
        float inter = ih * iw;
        float iou = inter / (areaR + areaC - inter + 1e-9f);
        if (iou > 0.7f) bits |= (1ull << c);
    }
    g_mask[((size_t)n * PRE_NMS + row) * 32 + cb] = bits;
}

// ---------------- serial NMS scan (register rem + shfl + deep prefetch) ----------------
#define NMS_PF 25            // prefetch depth; 2000 = 25 * 80
__global__ __launch_bounds__(32)
void nms_scan_kernel(float* __restrict__ out) {
    int n = blockIdx.x;
    int lane = threadIdx.x;
    const unsigned long long* M = g_mask + (size_t)n * PRE_NMS * 32;

    __shared__ int keep[POST_NMS];
    unsigned long long rem = 0ull;     // this lane's 64-column suppression chunk
    int cnt = 0;                        // replicated across lanes

    unsigned long long pre[NMS_PF];
#pragma unroll
    for (int u = 0; u < NMS_PF; u++) pre[u] = M[(size_t)u * 32 + lane];

    for (int base = 0; base < PRE_NMS; base += NMS_PF) {
#pragma unroll
        for (int u = 0; u < NMS_PF; u++) {
            int i = base + u;
            unsigned long long mrow = pre[u];
            int nx = i + NMS_PF;
            if (nx < PRE_NMS) pre[u] = M[(size_t)nx * 32 + lane];
            unsigned long long word = __shfl_sync(0xFFFFFFFFu, rem, i >> 6);
            bool sup = (word >> (i & 63)) & 1ull;
            if (!sup) {
                rem |= mrow;
                if (lane == 0 && cnt < POST_NMS) keep[cnt] = i;
                cnt++;
            }
        }
    }
    __syncwarp();
    int c = cnt < POST_NMS ? cnt : POST_NMS;

    for (int k = lane; k < POST_NMS; k += 32) {
        float4 b = make_float4(0, 0, 0, 0);
        if (k < c) b = *(const float4*)&g_topbox[((size_t)n * PRE_NMS + keep[k]) * 4];
        *(float4*)&out[OFF_ROIS + ((size_t)n * POST_NMS + k) * 4] = b;
        out[OFF_IDX + (size_t)n * POST_NMS + k] = (float)n;
    }
}

// ---------------- launch ----------------
extern "C" void kernel_launch(void* const* d_in, const int* in_sizes, int n_in,
                              void* d_out, int out_size) {
    const float* x   = (const float*)d_in[0];
    const float* c1w = (const float*)d_in[1];
    const float* c1b = (const float*)d_in[2];
    const float* sw  = (const float*)d_in[3];
    const float* sb  = (const float*)d_in[4];
    const float* lw  = (const float*)d_in[5];
    const float* lb  = (const float*)d_in[6];
    const int*   ih  = (const int*)d_in[7];
    const int*   iw  = (const int*)d_in[8];
    float* out = (float*)d_out;

    wtrans_kernel<<<(COUT * KKtot + 255) / 256, 256>>>(c1w);
    xpad_kernel<<<dim3((PADA + 255) / 256, NB * CIN), 256>>>(x);
    conv1_kernel<<<dim3(4, 256), 256>>>(c1b);
    conv1x1_kernel<<<512, 256>>>(lw, lb, sw, sb, out);
    decode_kernel<<<(NB * NANCH + 255) / 256, 256>>>(out, ih, iw);
    topk_kernel<<<NB, 1024>>>();
    iou_mask_kernel<<<dim3(32, 32, NB), 64>>>();
    nms_scan_kernel<<<NB, 32>>>(out);
}